// round 6
// baseline (speedup 1.0000x reference)
#include <cuda_runtime.h>
#include <math.h>
#include <stdint.h>

#define N_   8
#define CIN  512
#define MID  256
#define OUTC 256
#define H_   56
#define W_   56
#define P_   3136
#define PY_  784
#define K_   9
#define EPSF 1e-5f

// Scratch (static device globals; no allocation allowed)
__device__ float g_nhwc[(size_t)N_ * P_ * MID];       // xf in NHWC for gather
__device__ float g_off[(size_t)N_ * 18 * P_];         // offsets
__device__ float g_xf_scratch[(size_t)N_ * MID * P_]; // xf NCHW fallback
__device__ float g_wt[(size_t)OUTC * 2304];           // dcn weights, fragment-major tf32

// ---------------------------------------------------------------------------
// helpers (family-safe PTX only: sm_80+ instructions)
// ---------------------------------------------------------------------------
__device__ __forceinline__ float to_tf32(float x) {
    uint32_t u;
    asm("cvt.rna.tf32.f32 %0, %1;" : "=r"(u) : "f"(x));
    return __uint_as_float(u);
}
__device__ __forceinline__ void mma_tf32(float* d, const uint32_t* a, const uint32_t* b) {
    asm volatile(
        "mma.sync.aligned.m16n8k8.row.col.f32.tf32.tf32.f32 "
        "{%0,%1,%2,%3}, {%4,%5,%6,%7}, {%8,%9}, {%0,%1,%2,%3};"
        : "+f"(d[0]), "+f"(d[1]), "+f"(d[2]), "+f"(d[3])
        : "r"(a[0]), "r"(a[1]), "r"(a[2]), "r"(a[3]), "r"(b[0]), "r"(b[1]));
}
__device__ __forceinline__ uint32_t smem_u32(const void* p) {
    uint32_t a;
    asm("{ .reg .u64 t; cvta.to.shared.u64 t, %1; cvt.u32.u64 %0, t; }" : "=r"(a) : "l"(p));
    return a;
}
__device__ __forceinline__ void cp_async16(uint32_t dst, const void* src) {
    asm volatile("cp.async.cg.shared.global [%0], [%1], 16;" :: "r"(dst), "l"(src));
}
#define CP_COMMIT() asm volatile("cp.async.commit_group;" ::: "memory")
#define CP_WAIT0()  asm volatile("cp.async.wait_group 0;" ::: "memory")

// ---------------------------------------------------------------------------
// Kernel 0: rearrange dcn weights into fragment-major tf32 layout.
// g_wt[((og*72 + ch)*1024) + s*256 + m*128 + lane*4 + j]
//   = tf32( dw[o][c*9 + kk] ),
//   o = og*32 + m*16 + (lane>>2) + (j&1)*8
//   c = (ch&7)*32 + s*8 + (lane&3) + (j>>1)*4,  kk = ch>>3
// ---------------------------------------------------------------------------
__global__ void k0_wt(const float* __restrict__ dw)
{
    const int og = blockIdx.x / 72, ch = blockIdx.x % 72;
    const int kk = ch >> 3, c0 = (ch & 7) * 32;
    for (int t = threadIdx.x; t < 1024; t += 256) {
        int j = t & 3, lane = (t >> 2) & 31, m = (t >> 7) & 1, s = (t >> 8) & 3;
        int o = og * 32 + m * 16 + (lane >> 2) + (j & 1) * 8;
        int c = c0 + s * 8 + (lane & 3) + (j >> 1) * 4;
        g_wt[(size_t)blockIdx.x * 1024 + t] = to_tf32(dw[(size_t)o * 2304 + c * 9 + kk]);
    }
}

// ---------------------------------------------------------------------------
// Kernel 1: conv1(1x1,512->256) + BN1 + nearest-upsample(y) + attention fuse
// (unchanged from R2)
// ---------------------------------------------------------------------------
__global__ __launch_bounds__(256, 3)
void k1_fuse(const float* __restrict__ x, const float* __restrict__ y,
             const float* __restrict__ w1,
             const float* __restrict__ g1, const float* __restrict__ b1,
             const float* __restrict__ mu1, const float* __restrict__ v1,
             const float* __restrict__ attw, const float* __restrict__ attb,
             float* __restrict__ xf_nchw)
{
    extern __shared__ float sm[];
    float* xs   = sm;               // 512
    float* ws   = xs + 512;         // 4352
    float* yu_s = ws + 4352;        // 8448
    float* aw   = yu_s + 8448;      // 1024
    float* red  = aw + 1024;        // 256
    float* zs   = red + 256;        // 64

    const int n   = blockIdx.y;
    const int p0  = blockIdx.x * 32;
    const int tid = threadIdx.x;
    const int mlo = tid & 127;
    const int pb  = (tid >> 7) * 16;
    const int wid = tid >> 5;
    const int lane = tid & 31;

    float acc0[16], acc1[16];
#pragma unroll
    for (int j = 0; j < 16; j++) { acc0[j] = 0.f; acc1[j] = 0.f; }

    for (int i = tid; i < 1024; i += 256) aw[i] = attw[i];

    {
        const float* yb = y + (size_t)n * MID * PY_;
        for (int i = tid; i < 8192; i += 256) {
            int m = i >> 5, p = i & 31;
            int pgl = p0 + p;
            int hh = pgl / 56, ww = pgl % 56;
            int si = (hh >> 1) * 28 + (ww >> 1);
            yu_s[m * 33 + p] = yb[(size_t)m * PY_ + si];
        }
    }

    const float* xb = x + (size_t)n * CIN * P_ + p0;
    for (int c0 = 0; c0 < CIN; c0 += 16) {
        for (int i = tid; i < 512; i += 256) {
            int c = i >> 5, p = i & 31;
            xs[c * 32 + p] = xb[(size_t)(c0 + c) * P_ + p];
        }
        for (int i = tid; i < 4096; i += 256) {
            int m = i >> 4, cc = i & 15;
            ws[m * 17 + cc] = w1[m * 512 + c0 + cc];
        }
        __syncthreads();
#pragma unroll
        for (int cc = 0; cc < 16; cc++) {
            float wv0 = ws[mlo * 17 + cc];
            float wv1 = ws[(mlo + 128) * 17 + cc];
            const float4* xp = (const float4*)(xs + cc * 32 + pb);
#pragma unroll
            for (int u = 0; u < 4; u++) {
                float4 xv = xp[u];
                acc0[u*4+0] = fmaf(wv0, xv.x, acc0[u*4+0]);
                acc0[u*4+1] = fmaf(wv0, xv.y, acc0[u*4+1]);
                acc0[u*4+2] = fmaf(wv0, xv.z, acc0[u*4+2]);
                acc0[u*4+3] = fmaf(wv0, xv.w, acc0[u*4+3]);
                acc1[u*4+0] = fmaf(wv1, xv.x, acc1[u*4+0]);
                acc1[u*4+1] = fmaf(wv1, xv.y, acc1[u*4+1]);
                acc1[u*4+2] = fmaf(wv1, xv.z, acc1[u*4+2]);
                acc1[u*4+3] = fmaf(wv1, xv.w, acc1[u*4+3]);
            }
        }
        __syncthreads();
    }

    {
        float s0 = g1[mlo] * rsqrtf(v1[mlo] + EPSF);
        float bb0 = b1[mlo] - mu1[mlo] * s0;
        float s1 = g1[mlo + 128] * rsqrtf(v1[mlo + 128] + EPSF);
        float bb1 = b1[mlo + 128] - mu1[mlo + 128] * s1;
#pragma unroll
        for (int j = 0; j < 16; j++) {
            acc0[j] = fmaf(acc0[j], s0, bb0);
            acc1[j] = fmaf(acc1[j], s1, bb1);
        }
    }

    {
        float a00 = aw[mlo], a01 = aw[mlo + 128];
        float a10 = aw[256 + mlo], a11 = aw[256 + mlo + 128];
        float a20 = aw[512 + mlo], a21 = aw[512 + mlo + 128];
        float a30 = aw[768 + mlo], a31 = aw[768 + mlo + 128];
#pragma unroll
        for (int j = 0; j < 16; j++) {
            int p = pb + j;
            float yv0 = yu_s[mlo * 33 + p];
            float yv1 = yu_s[(mlo + 128) * 33 + p];
            float t0 = a00 * acc0[j] + a01 * acc1[j] + a10 * yv0 + a11 * yv1;
            float t1 = a20 * acc0[j] + a21 * acc1[j] + a30 * yv0 + a31 * yv1;
#pragma unroll
            for (int o = 16; o > 0; o >>= 1) {
                t0 += __shfl_xor_sync(0xffffffffu, t0, o);
                t1 += __shfl_xor_sync(0xffffffffu, t1, o);
            }
            if (lane == 0) {
                red[(wid * 16 + j) * 2 + 0] = t0;
                red[(wid * 16 + j) * 2 + 1] = t1;
            }
        }
    }
    __syncthreads();
    if (tid < 32) {
        int grp = tid >> 4, j = tid & 15;
        float s0 = 0.f, s1 = 0.f;
#pragma unroll
        for (int w = 0; w < 4; w++) {
            s0 += red[((grp * 4 + w) * 16 + j) * 2 + 0];
            s1 += red[((grp * 4 + w) * 16 + j) * 2 + 1];
        }
        zs[tid]      = 1.f / (1.f + expf(-(s0 + attb[0])));
        zs[32 + tid] = 1.f / (1.f + expf(-(s1 + attb[1])));
    }
    __syncthreads();

    float* xo0 = xf_nchw + ((size_t)(n * 256 + mlo)) * P_ + p0 + pb;
    float* xo1 = xf_nchw + ((size_t)(n * 256 + mlo + 128)) * P_ + p0 + pb;
    float* nh  = g_nhwc + ((size_t)n * P_ + p0 + pb) * 256;
#pragma unroll
    for (int j = 0; j < 16; j++) {
        int p = pb + j;
        float z0 = zs[p], z1 = zs[32 + p];
        float f0 = fmaf(acc0[j], z0, yu_s[mlo * 33 + p] * z1);
        float f1 = fmaf(acc1[j], z0, yu_s[(mlo + 128) * 33 + p] * z1);
        xo0[j] = f0;
        xo1[j] = f1;
        nh[(size_t)j * 256 + mlo] = f0;
        nh[(size_t)j * 256 + mlo + 128] = f1;
    }
}

// ---------------------------------------------------------------------------
// Kernel 2: offset conv3x3 (256 -> 18), pad 1. (unchanged from R2)
// ---------------------------------------------------------------------------
__global__ __launch_bounds__(256, 4)
void k2_off(const float* __restrict__ xf, const float* __restrict__ ow)
{
    __shared__ float xr[32 * 3 * 60];
    __shared__ float wr[18 * 289];

    const int h = blockIdx.x, n = blockIdx.y;
    const int tid = threadIdx.x;
    const int o = tid / 14, wg = tid % 14, wbase = wg * 4;

    float acc[4] = {0.f, 0.f, 0.f, 0.f};

    for (int c0 = 0; c0 < 256; c0 += 32) {
        for (int i = tid; i < 5568; i += 256) {
            int c = i / 174, rem = i % 174, r = rem / 58, colp = rem % 58;
            int row = h + r - 1, col = colp - 1;
            float v = 0.f;
            if (row >= 0 && row < 56 && col >= 0 && col < 56)
                v = xf[((size_t)(n * 256 + c0 + c)) * P_ + row * 56 + col];
            xr[c * 180 + r * 60 + colp] = v;
        }
        for (int i = tid; i < 5184; i += 256) {
            int oo = i / 288, rem = i % 288;
            wr[oo * 289 + rem] = ow[(size_t)oo * 2304 + c0 * 9 + rem];
        }
        __syncthreads();
        if (tid < 252) {
            for (int c = 0; c < 32; c++) {
#pragma unroll
                for (int ky = 0; ky < 3; ky++) {
                    const float4* rp = (const float4*)(xr + c * 180 + ky * 60 + wbase);
                    float4 A = rp[0], B = rp[1];
                    float xrow[6] = {A.x, A.y, A.z, A.w, B.x, B.y};
#pragma unroll
                    for (int kx = 0; kx < 3; kx++) {
                        float wv = wr[o * 289 + c * 9 + ky * 3 + kx];
#pragma unroll
                        for (int j = 0; j < 4; j++)
                            acc[j] = fmaf(wv, xrow[kx + j], acc[j]);
                    }
                }
            }
        }
        __syncthreads();
    }
    if (tid < 252) {
        float* ob = g_off + ((size_t)(n * 18 + o)) * P_ + h * 56 + wbase;
#pragma unroll
        for (int j = 0; j < 4; j++) ob[j] = acc[j];
    }
}

// ---------------------------------------------------------------------------
// Kernel 3: deformable conv via mma.sync tf32.
// 2 CTAs/SM: 256 threads, tile = 128 o x 64 px; grid (49, 8, 2).
// Weights pre-laid fragment-major -> A = LDS.128, sampled B k-paired -> LDS.64.
// 72 double-buffered chunks; cp.async weights; gather overlapped with MMA of
// the co-resident CTA.
// ---------------------------------------------------------------------------
#define A_BUF 4096                     // 4 og-local x 1024 floats
#define S_BUF 2560                     // 64 px x pitch 40
#define OFS_A   0                      // 2 x 4096 = 8192
#define OFS_S   (OFS_A + 2 * A_BUF)    // 2 x 2560 = 5120
#define OFS_MW  (OFS_S + 2 * S_BUF)    // 576 * 4 = 2304
#define OFS_MO  (OFS_MW + 2304)        // 2304
#define S3_FLOATS (OFS_MO + 2304)      // 17920 floats = 71680 B

__global__ __launch_bounds__(256, 2)
void k3_mma(const float* __restrict__ g2, const float* __restrict__ b2,
            const float* __restrict__ mu2, const float* __restrict__ v2,
            float* __restrict__ out)
{
    extern __shared__ float smf[];
    float*  abuf = smf + OFS_A;
    float*  sbuf = smf + OFS_S;
    float4* mw4  = (float4*)(smf + OFS_MW);
    int4*   mo4  = (int4*)(smf + OFS_MO);
    const uint32_t sA = smem_u32(smf + OFS_A);

    const int n   = blockIdx.y;
    const int oh  = blockIdx.z;          // o-half: 0 or 1
    const int p0  = blockIdx.x * 64;
    const int tid = threadIdx.x;
    const int wid = tid >> 5;
    const int lane = tid & 31;

    // bilinear metadata: 64 px x 9 taps = 576 entries
    for (int e = tid; e < 576; e += 256) {
        int p = e / 9, k = e - p * 9;
        int pg = p0 + p;
        int ph = pg / 56, pw = pg % 56;
        float dy = g_off[((size_t)(n * 18 + 2 * k)) * P_ + pg];
        float dx = g_off[((size_t)(n * 18 + 2 * k + 1)) * P_ + pg];
        float sy = (float)(ph - 1 + k / 3) + dy;
        float sx = (float)(pw - 1 + k % 3) + dx;
        float y0f = floorf(sy), x0f = floorf(sx);
        float wy1 = sy - y0f, wx1 = sx - x0f;
        int iy0 = (int)y0f, ix0 = (int)x0f;
        bool vy0 = (iy0 >= 0) && (iy0 <= 55);
        bool vy1 = (iy0 + 1 >= 0) && (iy0 + 1 <= 55);
        bool vx0 = (ix0 >= 0) && (ix0 <= 55);
        bool vx1 = (ix0 + 1 >= 0) && (ix0 + 1 <= 55);
        int y0c = min(max(iy0, 0), 55),     y1c = min(max(iy0 + 1, 0), 55);
        int x0c = min(max(ix0, 0), 55),     x1c = min(max(ix0 + 1, 0), 55);
        float4 w;
        w.x = (vy0 && vx0) ? (1.f - wy1) * (1.f - wx1) : 0.f;
        w.y = (vy0 && vx1) ? (1.f - wy1) * wx1 : 0.f;
        w.z = (vy1 && vx0) ? wy1 * (1.f - wx1) : 0.f;
        w.w = (vy1 && vx1) ? wy1 * wx1 : 0.f;
        int4 oo;
        oo.x = (y0c * 56 + x0c) * 256;
        oo.y = (y0c * 56 + x1c) * 256;
        oo.z = (y1c * 56 + x0c) * 256;
        oo.w = (y1c * 56 + x1c) * 256;
        mw4[e] = w;
        mo4[e] = oo;
    }
    __syncthreads();

    const float* nh = g_nhwc + (size_t)n * P_ * 256;
    const int g    = wid >> 1;          // og-local 0..3
    const int px0  = (wid & 1) * 32;    // px half
    const int qrow = lane >> 2;         // 0..7
    const int qcol = lane & 3;          // 0..3
    // sampled-B store position: pairs (k, k+4) adjacent within each 8-group
    const int spos = (lane >> 3) * 8 + (lane & 3) * 2 + ((lane & 7) >> 2);

    float acc[2][4][4];
#pragma unroll
    for (int m = 0; m < 2; m++)
#pragma unroll
        for (int t = 0; t < 4; t++)
#pragma unroll
            for (int c = 0; c < 4; c++) acc[m][t][c] = 0.f;

    auto weights_issue = [&](int buf, int ch) {
        const float* src = g_wt + ((size_t)(oh * 4) * 72 + ch) * 1024 + tid * 4;
        uint32_t dst = sA + (buf * A_BUF + tid * 4) * 4;
#pragma unroll
        for (int gl = 0; gl < 4; gl++)
            cp_async16(dst + gl * 4096, src + (size_t)gl * 72 * 1024);
        CP_COMMIT();
    };
    auto gather = [&](int buf, int ch) {
        const int kk = ch >> 3;
        const int ci = ((ch & 7) * 32) + lane;
        float* dst = sbuf + buf * S_BUF;
#pragma unroll
        for (int i = 0; i < 8; i++) {
            int p = wid * 8 + i;
            int e = p * 9 + kk;
            float4 w = mw4[e];
            int4  oo = mo4[e];
            float v = w.x * nh[oo.x + ci] + w.y * nh[oo.y + ci]
                    + w.z * nh[oo.z + ci] + w.w * nh[oo.w + ci];
            dst[p * 40 + spos] = to_tf32(v);
        }
    };
    auto do_mma = [&](int buf) {
        const float* Ab = abuf + buf * A_BUF;
        const float* Sb = sbuf + buf * S_BUF;
#pragma unroll
        for (int s = 0; s < 4; s++) {
            float4 av[2];
#pragma unroll
            for (int m = 0; m < 2; m++)
                av[m] = *(const float4*)(Ab + ((g * 4 + s) * 2 + m) * 128 + lane * 4);
            float2 bv[4];
            const float* sr = Sb + (px0 + qrow) * 40 + s * 8 + qcol * 2;
#pragma unroll
            for (int t = 0; t < 4; t++)
                bv[t] = *(const float2*)(sr + t * 8 * 40);
#pragma unroll
            for (int m = 0; m < 2; m++)
#pragma unroll
                for (int t = 0; t < 4; t++)
                    mma_tf32(acc[m][t], (const uint32_t*)&av[m], (const uint32_t*)&bv[t]);
        }
    };

    // prologue: chunk 0 -> buf 0
    weights_issue(0, 0);
    gather(0, 0);
    CP_WAIT0();
    __syncthreads();

    for (int ch = 0; ch < 72; ch++) {
        int b = ch & 1;
        bool more = (ch + 1 < 72);
        if (more) {
            weights_issue(b ^ 1, ch + 1);
            gather(b ^ 1, ch + 1);
        }
        do_mma(b);
        if (more) CP_WAIT0();
        __syncthreads();
    }

    // epilogue: BN2 + store
#pragma unroll
    for (int m = 0; m < 2; m++) {
#pragma unroll
        for (int rh = 0; rh < 2; rh++) {
            int o = oh * 128 + g * 32 + m * 16 + rh * 8 + qrow;
            float sc = g2[o] * rsqrtf(v2[o] + EPSF);
            float bi = b2[o] - mu2[o] * sc;
            float* ob = out + ((size_t)(n * 256 + o)) * P_ + p0 + px0;
#pragma unroll
            for (int t = 0; t < 4; t++) {
                float2 v;
                v.x = fmaf(acc[m][t][rh * 2 + 0], sc, bi);
                v.y = fmaf(acc[m][t][rh * 2 + 1], sc, bi);
                *(float2*)(ob + t * 8 + 2 * qcol) = v;
            }
        }
    }
}

// ---------------------------------------------------------------------------
extern "C" void kernel_launch(void* const* d_in, const int* in_sizes, int n_in,
                              void* d_out, int out_size)
{
    const float* x       = (const float*)d_in[0];
    const float* y       = (const float*)d_in[1];
    const float* conv1_w = (const float*)d_in[2];
    const float* bn1_g   = (const float*)d_in[3];
    const float* bn1_b   = (const float*)d_in[4];
    const float* bn1_m   = (const float*)d_in[5];
    const float* bn1_v   = (const float*)d_in[6];
    const float* att_w   = (const float*)d_in[7];
    const float* att_b   = (const float*)d_in[8];
    const float* off_w   = (const float*)d_in[9];
    const float* dcn_w   = (const float*)d_in[10];
    const float* bn2_g   = (const float*)d_in[11];
    const float* bn2_b   = (const float*)d_in[12];
    const float* bn2_m   = (const float*)d_in[13];
    const float* bn2_v   = (const float*)d_in[14];

    float* out = (float*)d_out;
    const size_t one = (size_t)N_ * OUTC * P_;  // 6,422,528

    float* xf_nchw;
    if ((size_t)out_size >= 2 * one) {
        xf_nchw = out + one;  // tuple (out, xf) flattened
    } else {
        void* p = nullptr;
        cudaGetSymbolAddress(&p, g_xf_scratch);
        xf_nchw = (float*)p;
    }

    cudaFuncSetAttribute(k1_fuse, cudaFuncAttributeMaxDynamicSharedMemorySize, 64 * 1024);
    cudaFuncSetAttribute(k3_mma,  cudaFuncAttributeMaxDynamicSharedMemorySize, S3_FLOATS * 4);

    k0_wt<<<576, 256>>>(dcn_w);

    const size_t smem1 = (512 + 4352 + 8448 + 1024 + 256 + 64) * 4; // 58,624
    k1_fuse<<<dim3(98, 8), 256, smem1>>>(x, y, conv1_w, bn1_g, bn1_b, bn1_m, bn1_v,
                                         att_w, att_b, xf_nchw);

    k2_off<<<dim3(56, 8), 256>>>(xf_nchw, off_w);

    k3_mma<<<dim3(49, 8, 2), 256, S3_FLOATS * 4>>>(bn2_g, bn2_b, bn2_m, bn2_v, out);
}

// round 7
// speedup vs baseline: 1.2693x; 1.2693x over previous
#include <cuda_runtime.h>
#include <math.h>
#include <stdint.h>

#define N_   8
#define CIN  512
#define MID  256
#define OUTC 256
#define H_   56
#define W_   56
#define P_   3136
#define PY_  784
#define K_   9
#define EPSF 1e-5f

// Scratch (static device globals; no allocation allowed)
__device__ float g_nhwc[(size_t)N_ * P_ * MID];       // xf in NHWC for gather
__device__ float g_off[(size_t)N_ * 18 * P_];         // offsets
__device__ float g_xf_scratch[(size_t)N_ * MID * P_]; // xf NCHW fallback
__device__ float g_wt[(size_t)OUTC * 2304];           // dcn weights, fragment-major tf32

// ---------------------------------------------------------------------------
// helpers (family-safe PTX only: sm_80+ instructions)
// ---------------------------------------------------------------------------
__device__ __forceinline__ float to_tf32(float x) {
    uint32_t u;
    asm("cvt.rna.tf32.f32 %0, %1;" : "=r"(u) : "f"(x));
    return __uint_as_float(u);
}
__device__ __forceinline__ void mma_tf32(float* d, const uint32_t* a, const uint32_t* b) {
    asm volatile(
        "mma.sync.aligned.m16n8k8.row.col.f32.tf32.tf32.f32 "
        "{%0,%1,%2,%3}, {%4,%5,%6,%7}, {%8,%9}, {%0,%1,%2,%3};"
        : "+f"(d[0]), "+f"(d[1]), "+f"(d[2]), "+f"(d[3])
        : "r"(a[0]), "r"(a[1]), "r"(a[2]), "r"(a[3]), "r"(b[0]), "r"(b[1]));
}
__device__ __forceinline__ uint32_t smem_u32(const void* p) {
    uint32_t a;
    asm("{ .reg .u64 t; cvta.to.shared.u64 t, %1; cvt.u32.u64 %0, t; }" : "=r"(a) : "l"(p));
    return a;
}
__device__ __forceinline__ void cp_async16(uint32_t dst, const void* src) {
    asm volatile("cp.async.cg.shared.global [%0], [%1], 16;" :: "r"(dst), "l"(src));
}
#define CP_COMMIT() asm volatile("cp.async.commit_group;" ::: "memory")
#define CP_WAIT0()  asm volatile("cp.async.wait_group 0;" ::: "memory")
#define CP_WAIT1()  asm volatile("cp.async.wait_group 1;" ::: "memory")

// ---------------------------------------------------------------------------
// Kernel 0: rearrange dcn weights into fragment-major tf32 layout.
// g_wt[((og*72 + ch)*1024) + s*256 + m*128 + lane*4 + j]
//   o = og*32 + m*16 + (lane>>2) + (j&1)*8
//   c = (ch&7)*32 + s*8 + (lane&3) + (j>>1)*4,  kk = ch>>3
// ---------------------------------------------------------------------------
__global__ void k0_wt(const float* __restrict__ dw)
{
    const int og = blockIdx.x / 72, ch = blockIdx.x % 72;
    const int kk = ch >> 3, c0 = (ch & 7) * 32;
    for (int t = threadIdx.x; t < 1024; t += 256) {
        int j = t & 3, lane = (t >> 2) & 31, m = (t >> 7) & 1, s = (t >> 8) & 3;
        int o = og * 32 + m * 16 + (lane >> 2) + (j & 1) * 8;
        int c = c0 + s * 8 + (lane & 3) + (j >> 1) * 4;
        g_wt[(size_t)blockIdx.x * 1024 + t] = to_tf32(dw[(size_t)o * 2304 + c * 9 + kk]);
    }
}

// ---------------------------------------------------------------------------
// Kernel 1: conv1(1x1,512->256) + BN1 + nearest-upsample(y) + attention fuse
// (unchanged from R2)
// ---------------------------------------------------------------------------
__global__ __launch_bounds__(256, 3)
void k1_fuse(const float* __restrict__ x, const float* __restrict__ y,
             const float* __restrict__ w1,
             const float* __restrict__ g1, const float* __restrict__ b1,
             const float* __restrict__ mu1, const float* __restrict__ v1,
             const float* __restrict__ attw, const float* __restrict__ attb,
             float* __restrict__ xf_nchw)
{
    extern __shared__ float sm[];
    float* xs   = sm;               // 512
    float* ws   = xs + 512;         // 4352
    float* yu_s = ws + 4352;        // 8448
    float* aw   = yu_s + 8448;      // 1024
    float* red  = aw + 1024;        // 256
    float* zs   = red + 256;        // 64

    const int n   = blockIdx.y;
    const int p0  = blockIdx.x * 32;
    const int tid = threadIdx.x;
    const int mlo = tid & 127;
    const int pb  = (tid >> 7) * 16;
    const int wid = tid >> 5;
    const int lane = tid & 31;

    float acc0[16], acc1[16];
#pragma unroll
    for (int j = 0; j < 16; j++) { acc0[j] = 0.f; acc1[j] = 0.f; }

    for (int i = tid; i < 1024; i += 256) aw[i] = attw[i];

    {
        const float* yb = y + (size_t)n * MID * PY_;
        for (int i = tid; i < 8192; i += 256) {
            int m = i >> 5, p = i & 31;
            int pgl = p0 + p;
            int hh = pgl / 56, ww = pgl % 56;
            int si = (hh >> 1) * 28 + (ww >> 1);
            yu_s[m * 33 + p] = yb[(size_t)m * PY_ + si];
        }
    }

    const float* xb = x + (size_t)n * CIN * P_ + p0;
    for (int c0 = 0; c0 < CIN; c0 += 16) {
        for (int i = tid; i < 512; i += 256) {
            int c = i >> 5, p = i & 31;
            xs[c * 32 + p] = xb[(size_t)(c0 + c) * P_ + p];
        }
        for (int i = tid; i < 4096; i += 256) {
            int m = i >> 4, cc = i & 15;
            ws[m * 17 + cc] = w1[m * 512 + c0 + cc];
        }
        __syncthreads();
#pragma unroll
        for (int cc = 0; cc < 16; cc++) {
            float wv0 = ws[mlo * 17 + cc];
            float wv1 = ws[(mlo + 128) * 17 + cc];
            const float4* xp = (const float4*)(xs + cc * 32 + pb);
#pragma unroll
            for (int u = 0; u < 4; u++) {
                float4 xv = xp[u];
                acc0[u*4+0] = fmaf(wv0, xv.x, acc0[u*4+0]);
                acc0[u*4+1] = fmaf(wv0, xv.y, acc0[u*4+1]);
                acc0[u*4+2] = fmaf(wv0, xv.z, acc0[u*4+2]);
                acc0[u*4+3] = fmaf(wv0, xv.w, acc0[u*4+3]);
                acc1[u*4+0] = fmaf(wv1, xv.x, acc1[u*4+0]);
                acc1[u*4+1] = fmaf(wv1, xv.y, acc1[u*4+1]);
                acc1[u*4+2] = fmaf(wv1, xv.z, acc1[u*4+2]);
                acc1[u*4+3] = fmaf(wv1, xv.w, acc1[u*4+3]);
            }
        }
        __syncthreads();
    }

    {
        float s0 = g1[mlo] * rsqrtf(v1[mlo] + EPSF);
        float bb0 = b1[mlo] - mu1[mlo] * s0;
        float s1 = g1[mlo + 128] * rsqrtf(v1[mlo + 128] + EPSF);
        float bb1 = b1[mlo + 128] - mu1[mlo + 128] * s1;
#pragma unroll
        for (int j = 0; j < 16; j++) {
            acc0[j] = fmaf(acc0[j], s0, bb0);
            acc1[j] = fmaf(acc1[j], s1, bb1);
        }
    }

    {
        float a00 = aw[mlo], a01 = aw[mlo + 128];
        float a10 = aw[256 + mlo], a11 = aw[256 + mlo + 128];
        float a20 = aw[512 + mlo], a21 = aw[512 + mlo + 128];
        float a30 = aw[768 + mlo], a31 = aw[768 + mlo + 128];
#pragma unroll
        for (int j = 0; j < 16; j++) {
            int p = pb + j;
            float yv0 = yu_s[mlo * 33 + p];
            float yv1 = yu_s[(mlo + 128) * 33 + p];
            float t0 = a00 * acc0[j] + a01 * acc1[j] + a10 * yv0 + a11 * yv1;
            float t1 = a20 * acc0[j] + a21 * acc1[j] + a30 * yv0 + a31 * yv1;
#pragma unroll
            for (int o = 16; o > 0; o >>= 1) {
                t0 += __shfl_xor_sync(0xffffffffu, t0, o);
                t1 += __shfl_xor_sync(0xffffffffu, t1, o);
            }
            if (lane == 0) {
                red[(wid * 16 + j) * 2 + 0] = t0;
                red[(wid * 16 + j) * 2 + 1] = t1;
            }
        }
    }
    __syncthreads();
    if (tid < 32) {
        int grp = tid >> 4, j = tid & 15;
        float s0 = 0.f, s1 = 0.f;
#pragma unroll
        for (int w = 0; w < 4; w++) {
            s0 += red[((grp * 4 + w) * 16 + j) * 2 + 0];
            s1 += red[((grp * 4 + w) * 16 + j) * 2 + 1];
        }
        zs[tid]      = 1.f / (1.f + expf(-(s0 + attb[0])));
        zs[32 + tid] = 1.f / (1.f + expf(-(s1 + attb[1])));
    }
    __syncthreads();

    float* xo0 = xf_nchw + ((size_t)(n * 256 + mlo)) * P_ + p0 + pb;
    float* xo1 = xf_nchw + ((size_t)(n * 256 + mlo + 128)) * P_ + p0 + pb;
    float* nh  = g_nhwc + ((size_t)n * P_ + p0 + pb) * 256;
#pragma unroll
    for (int j = 0; j < 16; j++) {
        int p = pb + j;
        float z0 = zs[p], z1 = zs[32 + p];
        float f0 = fmaf(acc0[j], z0, yu_s[mlo * 33 + p] * z1);
        float f1 = fmaf(acc1[j], z0, yu_s[(mlo + 128) * 33 + p] * z1);
        xo0[j] = f0;
        xo1[j] = f1;
        nh[(size_t)j * 256 + mlo] = f0;
        nh[(size_t)j * 256 + mlo + 128] = f1;
    }
}

// ---------------------------------------------------------------------------
// Kernel 2: offset conv3x3 (256 -> 18), pad 1. (unchanged from R2)
// ---------------------------------------------------------------------------
__global__ __launch_bounds__(256, 4)
void k2_off(const float* __restrict__ xf, const float* __restrict__ ow)
{
    __shared__ float xr[32 * 3 * 60];
    __shared__ float wr[18 * 289];

    const int h = blockIdx.x, n = blockIdx.y;
    const int tid = threadIdx.x;
    const int o = tid / 14, wg = tid % 14, wbase = wg * 4;

    float acc[4] = {0.f, 0.f, 0.f, 0.f};

    for (int c0 = 0; c0 < 256; c0 += 32) {
        for (int i = tid; i < 5568; i += 256) {
            int c = i / 174, rem = i % 174, r = rem / 58, colp = rem % 58;
            int row = h + r - 1, col = colp - 1;
            float v = 0.f;
            if (row >= 0 && row < 56 && col >= 0 && col < 56)
                v = xf[((size_t)(n * 256 + c0 + c)) * P_ + row * 56 + col];
            xr[c * 180 + r * 60 + colp] = v;
        }
        for (int i = tid; i < 5184; i += 256) {
            int oo = i / 288, rem = i % 288;
            wr[oo * 289 + rem] = ow[(size_t)oo * 2304 + c0 * 9 + rem];
        }
        __syncthreads();
        if (tid < 252) {
            for (int c = 0; c < 32; c++) {
#pragma unroll
                for (int ky = 0; ky < 3; ky++) {
                    const float4* rp = (const float4*)(xr + c * 180 + ky * 60 + wbase);
                    float4 A = rp[0], B = rp[1];
                    float xrow[6] = {A.x, A.y, A.z, A.w, B.x, B.y};
#pragma unroll
                    for (int kx = 0; kx < 3; kx++) {
                        float wv = wr[o * 289 + c * 9 + ky * 3 + kx];
#pragma unroll
                        for (int j = 0; j < 4; j++)
                            acc[j] = fmaf(wv, xrow[kx + j], acc[j]);
                    }
                }
            }
        }
        __syncthreads();
    }
    if (tid < 252) {
        float* ob = g_off + ((size_t)(n * 18 + o)) * P_ + h * 56 + wbase;
#pragma unroll
        for (int j = 0; j < 4; j++) ob[j] = acc[j];
    }
}

// ---------------------------------------------------------------------------
// Kernel 3: deformable conv via mma.sync tf32, deep pipeline.
// 512 threads, tile = 256 o x 64 px; grid (49, 8). 72 chunks (tap kk, 32 ch).
// Weights: fragment-major, 3-stage cp.async ring, wait_group 1.
// Gather: 2 chunks ahead in registers (st0/st1, unroll x2).
// A frags: LDS.128; B frags: k-paired LDS.64.
// ---------------------------------------------------------------------------
#define WCHUNK 8192                     // floats per weight chunk (256 o x 32 k)
#define SCHUNK 2560                     // floats per S buffer (64 px x pitch 40)
#define OFS_W   0                       // 3 x 8192 = 24576
#define OFS_S   (OFS_W + 3 * WCHUNK)    // 2 x 2560 = 5120
#define OFS_MW  (OFS_S + 2 * SCHUNK)    // 2304
#define OFS_MO  (OFS_MW + 2304)         // 2304
#define S3_FLOATS (OFS_MO + 2304)       // 34304 floats = 137216 B

__global__ __launch_bounds__(512, 1)
void k3_mma(const float* __restrict__ g2, const float* __restrict__ b2,
            const float* __restrict__ mu2, const float* __restrict__ v2,
            float* __restrict__ out)
{
    extern __shared__ float smf[];
    float*  wbuf = smf + OFS_W;
    float*  sbuf = smf + OFS_S;
    float4* mw4  = (float4*)(smf + OFS_MW);
    int4*   mo4  = (int4*)(smf + OFS_MO);
    const uint32_t sW = smem_u32(smf + OFS_W);

    const int n   = blockIdx.y;
    const int p0  = blockIdx.x * 64;
    const int tid = threadIdx.x;
    const int wid = tid >> 5;
    const int lane = tid & 31;

    // bilinear metadata: 64 px x 9 taps = 576 entries
    for (int e = tid; e < 576; e += 512) {
        int p = e / 9, k = e - p * 9;
        int pg = p0 + p;
        int ph = pg / 56, pw = pg % 56;
        float dy = g_off[((size_t)(n * 18 + 2 * k)) * P_ + pg];
        float dx = g_off[((size_t)(n * 18 + 2 * k + 1)) * P_ + pg];
        float sy = (float)(ph - 1 + k / 3) + dy;
        float sx = (float)(pw - 1 + k % 3) + dx;
        float y0f = floorf(sy), x0f = floorf(sx);
        float wy1 = sy - y0f, wx1 = sx - x0f;
        int iy0 = (int)y0f, ix0 = (int)x0f;
        bool vy0 = (iy0 >= 0) && (iy0 <= 55);
        bool vy1 = (iy0 + 1 >= 0) && (iy0 + 1 <= 55);
        bool vx0 = (ix0 >= 0) && (ix0 <= 55);
        bool vx1 = (ix0 + 1 >= 0) && (ix0 + 1 <= 55);
        int y0c = min(max(iy0, 0), 55),     y1c = min(max(iy0 + 1, 0), 55);
        int x0c = min(max(ix0, 0), 55),     x1c = min(max(ix0 + 1, 0), 55);
        float4 w;
        w.x = (vy0 && vx0) ? (1.f - wy1) * (1.f - wx1) : 0.f;
        w.y = (vy0 && vx1) ? (1.f - wy1) * wx1 : 0.f;
        w.z = (vy1 && vx0) ? wy1 * (1.f - wx1) : 0.f;
        w.w = (vy1 && vx1) ? wy1 * wx1 : 0.f;
        int4 oo;
        oo.x = (y0c * 56 + x0c) * 256;
        oo.y = (y0c * 56 + x1c) * 256;
        oo.z = (y1c * 56 + x0c) * 256;
        oo.w = (y1c * 56 + x1c) * 256;
        mw4[e] = w;
        mo4[e] = oo;
    }
    __syncthreads();

    const float* nh = g_nhwc + (size_t)n * P_ * 256;
    const int g    = wid >> 1;          // o-group 0..7
    const int px0  = (wid & 1) * 32;    // px half
    const int qrow = lane >> 2;
    const int qcol = lane & 3;
    const int spos = (lane >> 3) * 8 + (lane & 3) * 2 + ((lane & 7) >> 2);

    float acc[2][4][4];
#pragma unroll
    for (int m = 0; m < 2; m++)
#pragma unroll
        for (int t = 0; t < 4; t++)
#pragma unroll
            for (int c = 0; c < 4; c++) acc[m][t][c] = 0.f;

    float st0[16], st1[16];

    // weight issue: 8192 floats/chunk = 512 thr x 4 x float4
    auto weights_issue = [&](int slot, int ch) {
#pragma unroll
        for (int gl = 0; gl < 4; gl++) {
            int f = (gl * 512 + tid) * 4;           // 0..8188
            int og = f >> 10, inner = f & 1023;
            const float* src = g_wt + ((size_t)og * 72 + ch) * 1024 + inner;
            cp_async16(sW + (slot * WCHUNK + f) * 4, src);
        }
        CP_COMMIT();
    };
    auto gather_issue = [&](float* st, int ch) {
        const int kk = ch >> 3;
        const int ci = ((ch & 7) * 32) + lane;
#pragma unroll
        for (int i = 0; i < 4; i++) {
            int p = wid * 4 + i;
            int4 oo = mo4[p * 9 + kk];
            st[i*4+0] = nh[oo.x + ci];
            st[i*4+1] = nh[oo.y + ci];
            st[i*4+2] = nh[oo.z + ci];
            st[i*4+3] = nh[oo.w + ci];
        }
    };
    auto combine = [&](const float* st, int ch) {
        const int kk = ch >> 3;
        float* dst = sbuf + (ch & 1) * SCHUNK;
#pragma unroll
        for (int i = 0; i < 4; i++) {
            int p = wid * 4 + i;
            float4 w = mw4[p * 9 + kk];
            float v = w.x * st[i*4+0] + w.y * st[i*4+1]
                    + w.z * st[i*4+2] + w.w * st[i*4+3];
            dst[p * 40 + spos] = to_tf32(v);
        }
    };
    auto do_mma = [&](int ch) {
        const float* Ab = wbuf + (ch % 3) * WCHUNK + g * 1024;
        const float* Sb = sbuf + (ch & 1) * SCHUNK;
#pragma unroll
        for (int s = 0; s < 4; s++) {
            float4 av[2];
#pragma unroll
            for (int m = 0; m < 2; m++)
                av[m] = *(const float4*)(Ab + s * 256 + m * 128 + lane * 4);
            float2 bv[4];
            const float* sr = Sb + (px0 + qrow) * 40 + s * 8 + qcol * 2;
#pragma unroll
            for (int t = 0; t < 4; t++)
                bv[t] = *(const float2*)(sr + t * 8 * 40);
#pragma unroll
            for (int m = 0; m < 2; m++)
#pragma unroll
                for (int t = 0; t < 4; t++)
                    mma_tf32(acc[m][t], (const uint32_t*)&av[m], (const uint32_t*)&bv[t]);
        }
    };

    // prologue: weights 0,1 in flight; gather 0,1 in regs; S(0) combined
    weights_issue(0, 0);
    weights_issue(1, 1);
    gather_issue(st0, 0);
    gather_issue(st1, 1);
    combine(st0, 0);
    CP_WAIT1();           // W(0) complete
    __syncthreads();

    // main loop, unrolled x2 so register stages have compile-time indices
    auto iter = [&](int ch, float* stCur, float* stOther) {
        bool more2 = (ch + 2 < 72);
        if (more2) {
            weights_issue((ch + 2) % 3, ch + 2);
            gather_issue(stCur, ch + 2);
        }
        if (ch + 1 < 72) combine(stOther, ch + 1);
        do_mma(ch);
        if (more2) { CP_WAIT1(); }
        else if (ch + 1 < 72) { CP_WAIT0(); }
        __syncthreads();
    };
    for (int c2 = 0; c2 < 72; c2 += 2) {
        iter(c2,     st0, st1);
        iter(c2 + 1, st1, st0);
    }

    // epilogue: BN2 + store
#pragma unroll
    for (int m = 0; m < 2; m++) {
#pragma unroll
        for (int rh = 0; rh < 2; rh++) {
            int o = g * 32 + m * 16 + rh * 8 + qrow;
            float sc = g2[o] * rsqrtf(v2[o] + EPSF);
            float bi = b2[o] - mu2[o] * sc;
            float* ob = out + ((size_t)(n * 256 + o)) * P_ + p0 + px0;
#pragma unroll
            for (int t = 0; t < 4; t++) {
                float2 v;
                v.x = fmaf(acc[m][t][rh * 2 + 0], sc, bi);
                v.y = fmaf(acc[m][t][rh * 2 + 1], sc, bi);
                *(float2*)(ob + t * 8 + 2 * qcol) = v;
            }
        }
    }
}

// ---------------------------------------------------------------------------
extern "C" void kernel_launch(void* const* d_in, const int* in_sizes, int n_in,
                              void* d_out, int out_size)
{
    const float* x       = (const float*)d_in[0];
    const float* y       = (const float*)d_in[1];
    const float* conv1_w = (const float*)d_in[2];
    const float* bn1_g   = (const float*)d_in[3];
    const float* bn1_b   = (const float*)d_in[4];
    const float* bn1_m   = (const float*)d_in[5];
    const float* bn1_v   = (const float*)d_in[6];
    const float* att_w   = (const float*)d_in[7];
    const float* att_b   = (const float*)d_in[8];
    const float* off_w   = (const float*)d_in[9];
    const float* dcn_w   = (const float*)d_in[10];
    const float* bn2_g   = (const float*)d_in[11];
    const float* bn2_b   = (const float*)d_in[12];
    const float* bn2_m   = (const float*)d_in[13];
    const float* bn2_v   = (const float*)d_in[14];

    float* out = (float*)d_out;
    const size_t one = (size_t)N_ * OUTC * P_;  // 6,422,528

    float* xf_nchw;
    if ((size_t)out_size >= 2 * one) {
        xf_nchw = out + one;  // tuple (out, xf) flattened
    } else {
        void* p = nullptr;
        cudaGetSymbolAddress(&p, g_xf_scratch);
        xf_nchw = (float*)p;
    }

    cudaFuncSetAttribute(k1_fuse, cudaFuncAttributeMaxDynamicSharedMemorySize, 64 * 1024);
    cudaFuncSetAttribute(k3_mma,  cudaFuncAttributeMaxDynamicSharedMemorySize, 144 * 1024);

    k0_wt<<<576, 256>>>(dcn_w);

    const size_t smem1 = (512 + 4352 + 8448 + 1024 + 256 + 64) * 4; // 58,624
    k1_fuse<<<dim3(98, 8), 256, smem1>>>(x, y, conv1_w, bn1_g, bn1_b, bn1_m, bn1_v,
                                         att_w, att_b, xf_nchw);

    k2_off<<<dim3(56, 8), 256>>>(xf_nchw, off_w);

    k3_mma<<<dim3(49, 8), 512, S3_FLOATS * 4>>>(bn2_g, bn2_b, bn2_m, bn2_v, out);
}

// round 8
// speedup vs baseline: 1.7827x; 1.4045x over previous
#include <cuda_runtime.h>
#include <math.h>
#include <stdint.h>

#define N_   8
#define CIN  512
#define MID  256
#define OUTC 256
#define H_   56
#define W_   56
#define P_   3136
#define PY_  784
#define K_   9
#define EPSF 1e-5f

// Scratch (static device globals; no allocation allowed)
__device__ float g_nhwc[(size_t)N_ * P_ * MID];       // xf in NHWC for gather
__device__ float g_off[(size_t)N_ * 18 * P_];         // offsets
__device__ float g_xf_scratch[(size_t)N_ * MID * P_]; // xf NCHW fallback
__device__ float g_wt[(size_t)OUTC * 2304];           // dcn weights, fragment-major tf32
__device__ float g_w1t[(size_t)MID * CIN];            // conv1 weights, fragment-major tf32

// ---------------------------------------------------------------------------
// helpers (family-safe PTX only: sm_80+ instructions)
// ---------------------------------------------------------------------------
__device__ __forceinline__ float to_tf32(float x) {
    uint32_t u;
    asm("cvt.rna.tf32.f32 %0, %1;" : "=r"(u) : "f"(x));
    return __uint_as_float(u);
}
__device__ __forceinline__ uint32_t to_tf32u(float x) {
    uint32_t u;
    asm("cvt.rna.tf32.f32 %0, %1;" : "=r"(u) : "f"(x));
    return u;
}
__device__ __forceinline__ void mma_tf32(float* d, const uint32_t* a, const uint32_t* b) {
    asm volatile(
        "mma.sync.aligned.m16n8k8.row.col.f32.tf32.tf32.f32 "
        "{%0,%1,%2,%3}, {%4,%5,%6,%7}, {%8,%9}, {%0,%1,%2,%3};"
        : "+f"(d[0]), "+f"(d[1]), "+f"(d[2]), "+f"(d[3])
        : "r"(a[0]), "r"(a[1]), "r"(a[2]), "r"(a[3]), "r"(b[0]), "r"(b[1]));
}
__device__ __forceinline__ uint32_t smem_u32(const void* p) {
    uint32_t a;
    asm("{ .reg .u64 t; cvta.to.shared.u64 t, %1; cvt.u32.u64 %0, t; }" : "=r"(a) : "l"(p));
    return a;
}
__device__ __forceinline__ void cp_async16(uint32_t dst, const void* src) {
    asm volatile("cp.async.cg.shared.global [%0], [%1], 16;" :: "r"(dst), "l"(src));
}
#define CP_COMMIT() asm volatile("cp.async.commit_group;" ::: "memory")
#define CP_WAIT0()  asm volatile("cp.async.wait_group 0;" ::: "memory")
#define CP_WAIT1()  asm volatile("cp.async.wait_group 1;" ::: "memory")

// ---------------------------------------------------------------------------
// Kernel 0a: dcn weights -> fragment-major tf32 (72 chunks of (kk, 32c))
// ---------------------------------------------------------------------------
__global__ void k0_wt(const float* __restrict__ dw)
{
    const int og = blockIdx.x / 72, ch = blockIdx.x % 72;
    const int kk = ch >> 3, c0 = (ch & 7) * 32;
    for (int t = threadIdx.x; t < 1024; t += 256) {
        int j = t & 3, lane = (t >> 2) & 31, m = (t >> 7) & 1, s = (t >> 8) & 3;
        int o = og * 32 + m * 16 + (lane >> 2) + (j & 1) * 8;
        int c = c0 + s * 8 + (lane & 3) + (j >> 1) * 4;
        g_wt[(size_t)blockIdx.x * 1024 + t] = to_tf32(dw[(size_t)o * 2304 + c * 9 + kk]);
    }
}

// ---------------------------------------------------------------------------
// Kernel 0b: conv1 weights -> fragment-major tf32 (16 chunks of 32c)
// ---------------------------------------------------------------------------
__global__ void k0_w1(const float* __restrict__ w1)
{
    const int og = blockIdx.x >> 4, ch = blockIdx.x & 15;
    for (int t = threadIdx.x; t < 1024; t += 256) {
        int j = t & 3, lane = (t >> 2) & 31, m = (t >> 7) & 1, s = (t >> 8) & 3;
        int o = og * 32 + m * 16 + (lane >> 2) + (j & 1) * 8;
        int c = ch * 32 + s * 8 + (lane & 3) + (j >> 1) * 4;
        g_w1t[(size_t)blockIdx.x * 1024 + t] = to_tf32(w1[(size_t)o * 512 + c]);
    }
}

// ---------------------------------------------------------------------------
// Kernel 1: conv1 via mma.sync tf32 + BN1 + upsample + attention fuse.
// 512 threads, tile 256 m x 64 px, grid (49, 8). K=512 in 16 chunks of 32.
// Both operands via 3-stage cp.async ring. Fused epilogue writes xf NCHW+NHWC.
// ---------------------------------------------------------------------------
#define X_PITCH 72
#define XCHUNK (32 * X_PITCH)                  // 2304
#define K1_WCHUNK 8192
#define K1_OFS_W   0                           // 3 x 8192 = 24576
#define K1_OFS_X   (K1_OFS_W + 3 * K1_WCHUNK)  // 3 x 2304 = 6912
#define K1_OFS_AW  (K1_OFS_X + 3 * XCHUNK)     // 1024
#define K1_OFS_RED (K1_OFS_AW + 1024)          // 1024
#define K1_OFS_ZS  (K1_OFS_RED + 1024)         // 128
#define K1_OFS_SI  (K1_OFS_ZS + 128)           // 64
#define K1_FLOATS  (K1_OFS_SI + 64)            // 33792 floats = 135168 B
#define T_PITCH 260

__global__ __launch_bounds__(512, 1)
void k1_mma(const float* __restrict__ x, const float* __restrict__ y,
            const float* __restrict__ g1, const float* __restrict__ b1,
            const float* __restrict__ mu1, const float* __restrict__ v1,
            const float* __restrict__ attw, const float* __restrict__ attb,
            float* __restrict__ xf_nchw)
{
    extern __shared__ float smf[];
    float* wbuf = smf + K1_OFS_W;
    float* xbuf = smf + K1_OFS_X;
    float* aw   = smf + K1_OFS_AW;
    float* red  = smf + K1_OFS_RED;
    float* zs   = smf + K1_OFS_ZS;
    int*   si   = (int*)(smf + K1_OFS_SI);
    const uint32_t sB = smem_u32(smf);

    const int n   = blockIdx.y;
    const int p0  = blockIdx.x * 64;
    const int tid = threadIdx.x;
    const int wid = tid >> 5;
    const int lane = tid & 31;

    for (int i = tid; i < 1024; i += 512) aw[i] = attw[i];
    if (tid < 64) {
        int pg = p0 + tid;
        int hh = pg / 56, ww = pg % 56;
        si[tid] = (hh >> 1) * 28 + (ww >> 1);
    }

    const float* xb = x + (size_t)n * CIN * P_;
    const int xc  = tid >> 4, xseg = tid & 15;

    auto wi = [&](int slot, int ch) {
#pragma unroll
        for (int gl = 0; gl < 4; gl++) {
            int f = (gl * 512 + tid) * 4;
            int og = f >> 10, inner = f & 1023;
            cp_async16(sB + (uint32_t)(K1_OFS_W + slot * K1_WCHUNK + f) * 4,
                       g_w1t + ((size_t)og * 16 + ch) * 1024 + inner);
        }
    };
    auto xi = [&](int slot, int ch) {
        cp_async16(sB + (uint32_t)(K1_OFS_X + slot * XCHUNK + xc * X_PITCH + xseg * 4) * 4,
                   xb + (size_t)(ch * 32 + xc) * P_ + p0 + xseg * 4);
    };

    float acc[2][4][4];
#pragma unroll
    for (int m = 0; m < 2; m++)
#pragma unroll
        for (int t = 0; t < 4; t++)
#pragma unroll
            for (int c = 0; c < 4; c++) acc[m][t][c] = 0.f;

    // prologue
    wi(0, 0); xi(0, 0); CP_COMMIT();
    wi(1, 1); xi(1, 1); CP_COMMIT();
    CP_WAIT1();
    __syncthreads();

    const int g    = wid >> 1;
    const int px0  = (wid & 1) * 32;
    const int qrow = lane >> 2;
    const int qcol = lane & 3;

    for (int ch = 0; ch < 16; ch++) {
        int slot = ch % 3;
        bool more2 = (ch + 2 < 16);
        if (more2) { wi((ch + 2) % 3, ch + 2); xi((ch + 2) % 3, ch + 2); CP_COMMIT(); }
        const float* Ab = wbuf + slot * K1_WCHUNK + g * 1024;
        const float* Xc = xbuf + slot * XCHUNK;
#pragma unroll
        for (int s = 0; s < 4; s++) {
            float4 av[2];
#pragma unroll
            for (int m = 0; m < 2; m++)
                av[m] = *(const float4*)(Ab + s * 256 + m * 128 + lane * 4);
            uint32_t bb[4][2];
            const float* xr0 = Xc + (s * 8 + qcol) * X_PITCH + px0 + qrow;
            const float* xr1 = xr0 + 4 * X_PITCH;
#pragma unroll
            for (int t = 0; t < 4; t++) {
                bb[t][0] = to_tf32u(xr0[t * 8]);
                bb[t][1] = to_tf32u(xr1[t * 8]);
            }
#pragma unroll
            for (int m = 0; m < 2; m++)
#pragma unroll
                for (int t = 0; t < 4; t++)
                    mma_tf32(acc[m][t], (const uint32_t*)&av[m], bb[t]);
        }
        if (more2) { CP_WAIT1(); }
        else if (ch + 1 < 16) { CP_WAIT0(); }
        __syncthreads();
    }

    // ---- epilogue: BN1 + attention + sigmoid + xf, via smem transpose ----
    const float* yb = y + (size_t)n * MID * PY_;
    float t0p[8], t1p[8];
#pragma unroll
    for (int pj = 0; pj < 8; pj++) { t0p[pj] = 0.f; t1p[pj] = 0.f; }

#pragma unroll
    for (int m = 0; m < 2; m++) {
#pragma unroll
        for (int rh = 0; rh < 2; rh++) {
            int o = g * 32 + m * 16 + rh * 8 + qrow;
            float sc = g1[o] * rsqrtf(v1[o] + EPSF);
            float bi = b1[o] - mu1[o] * sc;
            float axm0 = aw[o], ayu0 = aw[256 + o];
            float axm1 = aw[512 + o], ayu1 = aw[768 + o];
#pragma unroll
            for (int t = 0; t < 4; t++) {
#pragma unroll
                for (int j = 0; j < 2; j++) {
                    int pj = t * 2 + j;
                    int p = px0 + t * 8 + qcol * 2 + j;
                    float xv = fmaf(acc[m][t][rh * 2 + j], sc, bi);
                    acc[m][t][rh * 2 + j] = xv;
                    float yv = yb[(size_t)o * PY_ + si[p]];
                    t0p[pj] = fmaf(axm0, xv, fmaf(ayu0, yv, t0p[pj]));
                    t1p[pj] = fmaf(axm1, xv, fmaf(ayu1, yv, t1p[pj]));
                }
            }
        }
    }
#pragma unroll
    for (int pj = 0; pj < 8; pj++) {
#pragma unroll
        for (int off = 4; off < 32; off <<= 1) {
            t0p[pj] += __shfl_xor_sync(0xffffffffu, t0p[pj], off);
            t1p[pj] += __shfl_xor_sync(0xffffffffu, t1p[pj], off);
        }
    }
    if (qrow == 0) {
#pragma unroll
        for (int t = 0; t < 4; t++)
#pragma unroll
            for (int j = 0; j < 2; j++) {
                int p = px0 + t * 8 + qcol * 2 + j;
                red[g * 64 + p]       = t0p[t * 2 + j];
                red[512 + g * 64 + p] = t1p[t * 2 + j];
            }
    }
    __syncthreads();
    if (tid < 128) {
        int which = tid & 1, p = tid >> 1;
        float s = 0.f;
#pragma unroll
        for (int gg = 0; gg < 8; gg++) s += red[which * 512 + gg * 64 + p];
        zs[which * 64 + p] = 1.f / (1.f + expf(-(s + attb[which])));
    }
    __syncthreads();

    float* trans = wbuf;   // [p][T_PITCH], 64*260 = 16640 floats
#pragma unroll
    for (int m = 0; m < 2; m++) {
#pragma unroll
        for (int rh = 0; rh < 2; rh++) {
            int o = g * 32 + m * 16 + rh * 8 + qrow;
#pragma unroll
            for (int t = 0; t < 4; t++) {
#pragma unroll
                for (int j = 0; j < 2; j++) {
                    int p = px0 + t * 8 + qcol * 2 + j;
                    float yv = yb[(size_t)o * PY_ + si[p]];
                    float xfv = acc[m][t][rh * 2 + j] * zs[p] + yv * zs[64 + p];
                    trans[p * T_PITCH + o] = xfv;
                }
            }
        }
    }
    __syncthreads();

    // NHWC write (coalesced): thread -> (p = tid>>3, 32 channels)
    {
        int p = tid >> 3, c0 = (tid & 7) * 32;
        float* dst = g_nhwc + ((size_t)n * P_ + p0 + p) * 256 + c0;
        const float* src = trans + p * T_PITCH + c0;
#pragma unroll
        for (int u = 0; u < 8; u++)
            *(float4*)(dst + u * 4) = *(const float4*)(src + u * 4);
    }
    // NCHW write: thread -> (o = tid>>1, 32 px half)
    {
        int o = tid >> 1, half = tid & 1;
        float* dst = xf_nchw + ((size_t)(n * 256 + o)) * P_ + p0 + half * 32;
#pragma unroll
        for (int u = 0; u < 8; u++) {
            float4 v;
            v.x = trans[(half * 32 + u * 4 + 0) * T_PITCH + o];
            v.y = trans[(half * 32 + u * 4 + 1) * T_PITCH + o];
            v.z = trans[(half * 32 + u * 4 + 2) * T_PITCH + o];
            v.w = trans[(half * 32 + u * 4 + 3) * T_PITCH + o];
            *(float4*)(dst + u * 4) = v;
        }
    }
}

// ---------------------------------------------------------------------------
// Kernel 2: offset conv3x3 (256 -> 18), pad 1. (unchanged)
// ---------------------------------------------------------------------------
__global__ __launch_bounds__(256, 4)
void k2_off(const float* __restrict__ xf, const float* __restrict__ ow)
{
    __shared__ float xr[32 * 3 * 60];
    __shared__ float wr[18 * 289];

    const int h = blockIdx.x, n = blockIdx.y;
    const int tid = threadIdx.x;
    const int o = tid / 14, wg = tid % 14, wbase = wg * 4;

    float acc[4] = {0.f, 0.f, 0.f, 0.f};

    for (int c0 = 0; c0 < 256; c0 += 32) {
        for (int i = tid; i < 5568; i += 256) {
            int c = i / 174, rem = i % 174, r = rem / 58, colp = rem % 58;
            int row = h + r - 1, col = colp - 1;
            float v = 0.f;
            if (row >= 0 && row < 56 && col >= 0 && col < 56)
                v = xf[((size_t)(n * 256 + c0 + c)) * P_ + row * 56 + col];
            xr[c * 180 + r * 60 + colp] = v;
        }
        for (int i = tid; i < 5184; i += 256) {
            int oo = i / 288, rem = i % 288;
            wr[oo * 289 + rem] = ow[(size_t)oo * 2304 + c0 * 9 + rem];
        }
        __syncthreads();
        if (tid < 252) {
            for (int c = 0; c < 32; c++) {
#pragma unroll
                for (int ky = 0; ky < 3; ky++) {
                    const float4* rp = (const float4*)(xr + c * 180 + ky * 60 + wbase);
                    float4 A = rp[0], B = rp[1];
                    float xrow[6] = {A.x, A.y, A.z, A.w, B.x, B.y};
#pragma unroll
                    for (int kx = 0; kx < 3; kx++) {
                        float wv = wr[o * 289 + c * 9 + ky * 3 + kx];
#pragma unroll
                        for (int j = 0; j < 4; j++)
                            acc[j] = fmaf(wv, xrow[kx + j], acc[j]);
                    }
                }
            }
        }
        __syncthreads();
    }
    if (tid < 252) {
        float* ob = g_off + ((size_t)(n * 18 + o)) * P_ + h * 56 + wbase;
#pragma unroll
        for (int j = 0; j < 4; j++) ob[j] = acc[j];
    }
}

// ---------------------------------------------------------------------------
// Kernel 3: deformable conv via mma.sync tf32, deep pipeline. (unchanged R7)
// ---------------------------------------------------------------------------
#define WCHUNK 8192
#define SCHUNK 2560
#define OFS_W   0
#define OFS_S   (OFS_W + 3 * WCHUNK)
#define OFS_MW  (OFS_S + 2 * SCHUNK)
#define OFS_MO  (OFS_MW + 2304)
#define S3_FLOATS (OFS_MO + 2304)

__global__ __launch_bounds__(512, 1)
void k3_mma(const float* __restrict__ g2, const float* __restrict__ b2,
            const float* __restrict__ mu2, const float* __restrict__ v2,
            float* __restrict__ out)
{
    extern __shared__ float smf[];
    float*  wbuf = smf + OFS_W;
    float*  sbuf = smf + OFS_S;
    float4* mw4  = (float4*)(smf + OFS_MW);
    int4*   mo4  = (int4*)(smf + OFS_MO);
    const uint32_t sW = smem_u32(smf + OFS_W);

    const int n   = blockIdx.y;
    const int p0  = blockIdx.x * 64;
    const int tid = threadIdx.x;
    const int wid = tid >> 5;
    const int lane = tid & 31;

    for (int e = tid; e < 576; e += 512) {
        int p = e / 9, k = e - p * 9;
        int pg = p0 + p;
        int ph = pg / 56, pw = pg % 56;
        float dy = g_off[((size_t)(n * 18 + 2 * k)) * P_ + pg];
        float dx = g_off[((size_t)(n * 18 + 2 * k + 1)) * P_ + pg];
        float sy = (float)(ph - 1 + k / 3) + dy;
        float sx = (float)(pw - 1 + k % 3) + dx;
        float y0f = floorf(sy), x0f = floorf(sx);
        float wy1 = sy - y0f, wx1 = sx - x0f;
        int iy0 = (int)y0f, ix0 = (int)x0f;
        bool vy0 = (iy0 >= 0) && (iy0 <= 55);
        bool vy1 = (iy0 + 1 >= 0) && (iy0 + 1 <= 55);
        bool vx0 = (ix0 >= 0) && (ix0 <= 55);
        bool vx1 = (ix0 + 1 >= 0) && (ix0 + 1 <= 55);
        int y0c = min(max(iy0, 0), 55),     y1c = min(max(iy0 + 1, 0), 55);
        int x0c = min(max(ix0, 0), 55),     x1c = min(max(ix0 + 1, 0), 55);
        float4 w;
        w.x = (vy0 && vx0) ? (1.f - wy1) * (1.f - wx1) : 0.f;
        w.y = (vy0 && vx1) ? (1.f - wy1) * wx1 : 0.f;
        w.z = (vy1 && vx0) ? wy1 * (1.f - wx1) : 0.f;
        w.w = (vy1 && vx1) ? wy1 * wx1 : 0.f;
        int4 oo;
        oo.x = (y0c * 56 + x0c) * 256;
        oo.y = (y0c * 56 + x1c) * 256;
        oo.z = (y1c * 56 + x0c) * 256;
        oo.w = (y1c * 56 + x1c) * 256;
        mw4[e] = w;
        mo4[e] = oo;
    }
    __syncthreads();

    const float* nh = g_nhwc + (size_t)n * P_ * 256;
    const int g    = wid >> 1;
    const int px0  = (wid & 1) * 32;
    const int qrow = lane >> 2;
    const int qcol = lane & 3;
    const int spos = (lane >> 3) * 8 + (lane & 3) * 2 + ((lane & 7) >> 2);

    float acc[2][4][4];
#pragma unroll
    for (int m = 0; m < 2; m++)
#pragma unroll
        for (int t = 0; t < 4; t++)
#pragma unroll
            for (int c = 0; c < 4; c++) acc[m][t][c] = 0.f;

    float st0[16], st1[16];

    auto weights_issue = [&](int slot, int ch) {
#pragma unroll
        for (int gl = 0; gl < 4; gl++) {
            int f = (gl * 512 + tid) * 4;
            int og = f >> 10, inner = f & 1023;
            const float* src = g_wt + ((size_t)og * 72 + ch) * 1024 + inner;
            cp_async16(sW + (slot * WCHUNK + f) * 4, src);
        }
        CP_COMMIT();
    };
    auto gather_issue = [&](float* st, int ch) {
        const int kk = ch >> 3;
        const int ci = ((ch & 7) * 32) + lane;
#pragma unroll
        for (int i = 0; i < 4; i++) {
            int p = wid * 4 + i;
            int4 oo = mo4[p * 9 + kk];
            st[i*4+0] = nh[oo.x + ci];
            st[i*4+1] = nh[oo.y + ci];
            st[i*4+2] = nh[oo.z + ci];
            st[i*4+3] = nh[oo.w + ci];
        }
    };
    auto combine = [&](const float* st, int ch) {
        const int kk = ch >> 3;
        float* dst = sbuf + (ch & 1) * SCHUNK;
#pragma unroll
        for (int i = 0; i < 4; i++) {
            int p = wid * 4 + i;
            float4 w = mw4[p * 9 + kk];
            float v = w.x * st[i*4+0] + w.y * st[i*4+1]
                    + w.z * st[i*4+2] + w.w * st[i*4+3];
            dst[p * 40 + spos] = to_tf32(v);
        }
    };
    auto do_mma = [&](int ch) {
        const float* Ab = wbuf + (ch % 3) * WCHUNK + g * 1024;
        const float* Sb = sbuf + (ch & 1) * SCHUNK;
#pragma unroll
        for (int s = 0; s < 4; s++) {
            float4 av[2];
#pragma unroll
            for (int m = 0; m < 2; m++)
                av[m] = *(const float4*)(Ab + s * 256 + m * 128 + lane * 4);
            float2 bv[4];
            const float* sr = Sb + (px0 + qrow) * 40 + s * 8 + qcol * 2;
#pragma unroll
            for (int t = 0; t < 4; t++)
                bv[t] = *(const float2*)(sr + t * 8 * 40);
#pragma unroll
            for (int m = 0; m < 2; m++)
#pragma unroll
                for (int t = 0; t < 4; t++)
                    mma_tf32(acc[m][t], (const uint32_t*)&av[m], (const uint32_t*)&bv[t]);
        }
    };

    weights_issue(0, 0);
    weights_issue(1, 1);
    gather_issue(st0, 0);
    gather_issue(st1, 1);
    combine(st0, 0);
    CP_WAIT1();
    __syncthreads();

    auto iter = [&](int ch, float* stCur, float* stOther) {
        bool more2 = (ch + 2 < 72);
        if (more2) {
            weights_issue((ch + 2) % 3, ch + 2);
            gather_issue(stCur, ch + 2);
        }
        if (ch + 1 < 72) combine(stOther, ch + 1);
        do_mma(ch);
        if (more2) { CP_WAIT1(); }
        else if (ch + 1 < 72) { CP_WAIT0(); }
        __syncthreads();
    };
    for (int c2 = 0; c2 < 72; c2 += 2) {
        iter(c2,     st0, st1);
        iter(c2 + 1, st1, st0);
    }

#pragma unroll
    for (int m = 0; m < 2; m++) {
#pragma unroll
        for (int rh = 0; rh < 2; rh++) {
            int o = g * 32 + m * 16 + rh * 8 + qrow;
            float sc = g2[o] * rsqrtf(v2[o] + EPSF);
            float bi = b2[o] - mu2[o] * sc;
            float* ob = out + ((size_t)(n * 256 + o)) * P_ + p0 + px0;
#pragma unroll
            for (int t = 0; t < 4; t++) {
                float2 v;
                v.x = fmaf(acc[m][t][rh * 2 + 0], sc, bi);
                v.y = fmaf(acc[m][t][rh * 2 + 1], sc, bi);
                *(float2*)(ob + t * 8 + 2 * qcol) = v;
            }
        }
    }
}

// ---------------------------------------------------------------------------
extern "C" void kernel_launch(void* const* d_in, const int* in_sizes, int n_in,
                              void* d_out, int out_size)
{
    const float* x       = (const float*)d_in[0];
    const float* y       = (const float*)d_in[1];
    const float* conv1_w = (const float*)d_in[2];
    const float* bn1_g   = (const float*)d_in[3];
    const float* bn1_b   = (const float*)d_in[4];
    const float* bn1_m   = (const float*)d_in[5];
    const float* bn1_v   = (const float*)d_in[6];
    const float* att_w   = (const float*)d_in[7];
    const float* att_b   = (const float*)d_in[8];
    const float* off_w   = (const float*)d_in[9];
    const float* dcn_w   = (const float*)d_in[10];
    const float* bn2_g   = (const float*)d_in[11];
    const float* bn2_b   = (const float*)d_in[12];
    const float* bn2_m   = (const float*)d_in[13];
    const float* bn2_v   = (const float*)d_in[14];

    float* out = (float*)d_out;
    const size_t one = (size_t)N_ * OUTC * P_;  // 6,422,528

    float* xf_nchw;
    if ((size_t)out_size >= 2 * one) {
        xf_nchw = out + one;  // tuple (out, xf) flattened
    } else {
        void* p = nullptr;
        cudaGetSymbolAddress(&p, g_xf_scratch);
        xf_nchw = (float*)p;
    }

    cudaFuncSetAttribute(k1_mma, cudaFuncAttributeMaxDynamicSharedMemorySize, 140 * 1024);
    cudaFuncSetAttribute(k3_mma, cudaFuncAttributeMaxDynamicSharedMemorySize, 144 * 1024);

    k0_wt<<<576, 256>>>(dcn_w);
    k0_w1<<<128, 256>>>(conv1_w);

    k1_mma<<<dim3(49, 8), 512, K1_FLOATS * 4>>>(x, y, bn1_g, bn1_b, bn1_m, bn1_v,
                                                att_w, att_b, xf_nchw);

    k2_off<<<dim3(56, 8), 256>>>(xf_nchw, off_w);

    k3_mma<<<dim3(49, 8), 512, S3_FLOATS * 4>>>(bn2_g, bn2_b, bn2_m, bn2_v, out);
}

// round 9
// speedup vs baseline: 1.8863x; 1.0581x over previous
#include <cuda_runtime.h>
#include <math.h>
#include <stdint.h>

#define N_   8
#define CIN  512
#define MID  256
#define OUTC 256
#define H_   56
#define W_   56
#define P_   3136
#define PY_  784
#define K_   9
#define EPSF 1e-5f

// Scratch (static device globals; no allocation allowed)
__device__ float g_nhwc[(size_t)N_ * P_ * MID];       // xf in NHWC for gather
__device__ float g_off[(size_t)N_ * 18 * P_];         // offsets
__device__ float g_xf_scratch[(size_t)N_ * MID * P_]; // xf NCHW fallback
__device__ float g_wt[(size_t)OUTC * 2304];           // dcn weights, fragment-major tf32
__device__ float g_w1t[(size_t)MID * CIN];            // conv1 weights, fragment-major tf32
__device__ float g_w2t[(size_t)72 * 1024];            // offset-conv weights, fragment-major tf32 (M pad 32)

// ---------------------------------------------------------------------------
// helpers (family-safe PTX only: sm_80+ instructions)
// ---------------------------------------------------------------------------
__device__ __forceinline__ float to_tf32(float x) {
    uint32_t u;
    asm("cvt.rna.tf32.f32 %0, %1;" : "=r"(u) : "f"(x));
    return __uint_as_float(u);
}
__device__ __forceinline__ uint32_t to_tf32u(float x) {
    uint32_t u;
    asm("cvt.rna.tf32.f32 %0, %1;" : "=r"(u) : "f"(x));
    return u;
}
__device__ __forceinline__ void mma_tf32(float* d, const uint32_t* a, const uint32_t* b) {
    asm volatile(
        "mma.sync.aligned.m16n8k8.row.col.f32.tf32.tf32.f32 "
        "{%0,%1,%2,%3}, {%4,%5,%6,%7}, {%8,%9}, {%0,%1,%2,%3};"
        : "+f"(d[0]), "+f"(d[1]), "+f"(d[2]), "+f"(d[3])
        : "r"(a[0]), "r"(a[1]), "r"(a[2]), "r"(a[3]), "r"(b[0]), "r"(b[1]));
}
__device__ __forceinline__ uint32_t smem_u32(const void* p) {
    uint32_t a;
    asm("{ .reg .u64 t; cvta.to.shared.u64 t, %1; cvt.u32.u64 %0, t; }" : "=r"(a) : "l"(p));
    return a;
}
__device__ __forceinline__ void cp_async16(uint32_t dst, const void* src) {
    asm volatile("cp.async.cg.shared.global [%0], [%1], 16;" :: "r"(dst), "l"(src));
}
#define CP_COMMIT() asm volatile("cp.async.commit_group;" ::: "memory")
#define CP_WAIT0()  asm volatile("cp.async.wait_group 0;" ::: "memory")
#define CP_WAIT1()  asm volatile("cp.async.wait_group 1;" ::: "memory")

// ---------------------------------------------------------------------------
// Kernel 0a: dcn weights -> fragment-major tf32 (72 chunks of (kk, 32c))
// ---------------------------------------------------------------------------
__global__ void k0_wt(const float* __restrict__ dw)
{
    const int og = blockIdx.x / 72, ch = blockIdx.x % 72;
    const int kk = ch >> 3, c0 = (ch & 7) * 32;
    for (int t = threadIdx.x; t < 1024; t += 256) {
        int j = t & 3, lane = (t >> 2) & 31, m = (t >> 7) & 1, s = (t >> 8) & 3;
        int o = og * 32 + m * 16 + (lane >> 2) + (j & 1) * 8;
        int c = c0 + s * 8 + (lane & 3) + (j >> 1) * 4;
        g_wt[(size_t)blockIdx.x * 1024 + t] = to_tf32(dw[(size_t)o * 2304 + c * 9 + kk]);
    }
}

// ---------------------------------------------------------------------------
// Kernel 0b: conv1 weights -> fragment-major tf32 (16 chunks of 32c)
// ---------------------------------------------------------------------------
__global__ void k0_w1(const float* __restrict__ w1)
{
    const int og = blockIdx.x >> 4, ch = blockIdx.x & 15;
    for (int t = threadIdx.x; t < 1024; t += 256) {
        int j = t & 3, lane = (t >> 2) & 31, m = (t >> 7) & 1, s = (t >> 8) & 3;
        int o = og * 32 + m * 16 + (lane >> 2) + (j & 1) * 8;
        int c = ch * 32 + s * 8 + (lane & 3) + (j >> 1) * 4;
        g_w1t[(size_t)blockIdx.x * 1024 + t] = to_tf32(w1[(size_t)o * 512 + c]);
    }
}

// ---------------------------------------------------------------------------
// Kernel 0c: offset-conv weights (18 -> pad 32) -> fragment-major tf32
// off_w is OIHW (18,256,3,3): off_w[o][c*9+kk] like dcn.
// ---------------------------------------------------------------------------
__global__ void k0_w2(const float* __restrict__ ow)
{
    const int ch = blockIdx.x;            // 72 chunks
    const int kk = ch >> 3, c0 = (ch & 7) * 32;
    for (int t = threadIdx.x; t < 1024; t += 256) {
        int j = t & 3, lane = (t >> 2) & 31, m = (t >> 7) & 1, s = (t >> 8) & 3;
        int o = m * 16 + (lane >> 2) + (j & 1) * 8;
        int c = c0 + s * 8 + (lane & 3) + (j >> 1) * 4;
        float v = (o < 18) ? ow[(size_t)o * 2304 + c * 9 + kk] : 0.f;
        g_w2t[(size_t)ch * 1024 + t] = to_tf32(v);
    }
}

// ---------------------------------------------------------------------------
// Kernel 1: conv1 via mma.sync tf32 + BN1 + upsample + attention fuse.
// (unchanged from R8)
// ---------------------------------------------------------------------------
#define X_PITCH 72
#define XCHUNK (32 * X_PITCH)
#define K1_WCHUNK 8192
#define K1_OFS_W   0
#define K1_OFS_X   (K1_OFS_W + 3 * K1_WCHUNK)
#define K1_OFS_AW  (K1_OFS_X + 3 * XCHUNK)
#define K1_OFS_RED (K1_OFS_AW + 1024)
#define K1_OFS_ZS  (K1_OFS_RED + 1024)
#define K1_OFS_SI  (K1_OFS_ZS + 128)
#define K1_FLOATS  (K1_OFS_SI + 64)
#define T_PITCH 260

__global__ __launch_bounds__(512, 1)
void k1_mma(const float* __restrict__ x, const float* __restrict__ y,
            const float* __restrict__ g1, const float* __restrict__ b1,
            const float* __restrict__ mu1, const float* __restrict__ v1,
            const float* __restrict__ attw, const float* __restrict__ attb,
            float* __restrict__ xf_nchw)
{
    extern __shared__ float smf[];
    float* wbuf = smf + K1_OFS_W;
    float* xbuf = smf + K1_OFS_X;
    float* aw   = smf + K1_OFS_AW;
    float* red  = smf + K1_OFS_RED;
    float* zs   = smf + K1_OFS_ZS;
    int*   si   = (int*)(smf + K1_OFS_SI);
    const uint32_t sB = smem_u32(smf);

    const int n   = blockIdx.y;
    const int p0  = blockIdx.x * 64;
    const int tid = threadIdx.x;
    const int wid = tid >> 5;
    const int lane = tid & 31;

    for (int i = tid; i < 1024; i += 512) aw[i] = attw[i];
    if (tid < 64) {
        int pg = p0 + tid;
        int hh = pg / 56, ww = pg % 56;
        si[tid] = (hh >> 1) * 28 + (ww >> 1);
    }

    const float* xb = x + (size_t)n * CIN * P_;
    const int xc  = tid >> 4, xseg = tid & 15;

    auto wi = [&](int slot, int ch) {
#pragma unroll
        for (int gl = 0; gl < 4; gl++) {
            int f = (gl * 512 + tid) * 4;
            int og = f >> 10, inner = f & 1023;
            cp_async16(sB + (uint32_t)(K1_OFS_W + slot * K1_WCHUNK + f) * 4,
                       g_w1t + ((size_t)og * 16 + ch) * 1024 + inner);
        }
    };
    auto xi = [&](int slot, int ch) {
        cp_async16(sB + (uint32_t)(K1_OFS_X + slot * XCHUNK + xc * X_PITCH + xseg * 4) * 4,
                   xb + (size_t)(ch * 32 + xc) * P_ + p0 + xseg * 4);
    };

    float acc[2][4][4];
#pragma unroll
    for (int m = 0; m < 2; m++)
#pragma unroll
        for (int t = 0; t < 4; t++)
#pragma unroll
            for (int c = 0; c < 4; c++) acc[m][t][c] = 0.f;

    wi(0, 0); xi(0, 0); CP_COMMIT();
    wi(1, 1); xi(1, 1); CP_COMMIT();
    CP_WAIT1();
    __syncthreads();

    const int g    = wid >> 1;
    const int px0  = (wid & 1) * 32;
    const int qrow = lane >> 2;
    const int qcol = lane & 3;

    for (int ch = 0; ch < 16; ch++) {
        int slot = ch % 3;
        bool more2 = (ch + 2 < 16);
        if (more2) { wi((ch + 2) % 3, ch + 2); xi((ch + 2) % 3, ch + 2); CP_COMMIT(); }
        const float* Ab = wbuf + slot * K1_WCHUNK + g * 1024;
        const float* Xc = xbuf + slot * XCHUNK;
#pragma unroll
        for (int s = 0; s < 4; s++) {
            float4 av[2];
#pragma unroll
            for (int m = 0; m < 2; m++)
                av[m] = *(const float4*)(Ab + s * 256 + m * 128 + lane * 4);
            uint32_t bb[4][2];
            const float* xr0 = Xc + (s * 8 + qcol) * X_PITCH + px0 + qrow;
            const float* xr1 = xr0 + 4 * X_PITCH;
#pragma unroll
            for (int t = 0; t < 4; t++) {
                bb[t][0] = to_tf32u(xr0[t * 8]);
                bb[t][1] = to_tf32u(xr1[t * 8]);
            }
#pragma unroll
            for (int m = 0; m < 2; m++)
#pragma unroll
                for (int t = 0; t < 4; t++)
                    mma_tf32(acc[m][t], (const uint32_t*)&av[m], bb[t]);
        }
        if (more2) { CP_WAIT1(); }
        else if (ch + 1 < 16) { CP_WAIT0(); }
        __syncthreads();
    }

    const float* yb = y + (size_t)n * MID * PY_;
    float t0p[8], t1p[8];
#pragma unroll
    for (int pj = 0; pj < 8; pj++) { t0p[pj] = 0.f; t1p[pj] = 0.f; }

#pragma unroll
    for (int m = 0; m < 2; m++) {
#pragma unroll
        for (int rh = 0; rh < 2; rh++) {
            int o = g * 32 + m * 16 + rh * 8 + qrow;
            float sc = g1[o] * rsqrtf(v1[o] + EPSF);
            float bi = b1[o] - mu1[o] * sc;
            float axm0 = aw[o], ayu0 = aw[256 + o];
            float axm1 = aw[512 + o], ayu1 = aw[768 + o];
#pragma unroll
            for (int t = 0; t < 4; t++) {
#pragma unroll
                for (int j = 0; j < 2; j++) {
                    int pj = t * 2 + j;
                    int p = px0 + t * 8 + qcol * 2 + j;
                    float xv = fmaf(acc[m][t][rh * 2 + j], sc, bi);
                    acc[m][t][rh * 2 + j] = xv;
                    float yv = yb[(size_t)o * PY_ + si[p]];
                    t0p[pj] = fmaf(axm0, xv, fmaf(ayu0, yv, t0p[pj]));
                    t1p[pj] = fmaf(axm1, xv, fmaf(ayu1, yv, t1p[pj]));
                }
            }
        }
    }
#pragma unroll
    for (int pj = 0; pj < 8; pj++) {
#pragma unroll
        for (int off = 4; off < 32; off <<= 1) {
            t0p[pj] += __shfl_xor_sync(0xffffffffu, t0p[pj], off);
            t1p[pj] += __shfl_xor_sync(0xffffffffu, t1p[pj], off);
        }
    }
    if (qrow == 0) {
#pragma unroll
        for (int t = 0; t < 4; t++)
#pragma unroll
            for (int j = 0; j < 2; j++) {
                int p = px0 + t * 8 + qcol * 2 + j;
                red[g * 64 + p]       = t0p[t * 2 + j];
                red[512 + g * 64 + p] = t1p[t * 2 + j];
            }
    }
    __syncthreads();
    if (tid < 128) {
        int which = tid & 1, p = tid >> 1;
        float s = 0.f;
#pragma unroll
        for (int gg = 0; gg < 8; gg++) s += red[which * 512 + gg * 64 + p];
        zs[which * 64 + p] = 1.f / (1.f + expf(-(s + attb[which])));
    }
    __syncthreads();

    float* trans = wbuf;
#pragma unroll
    for (int m = 0; m < 2; m++) {
#pragma unroll
        for (int rh = 0; rh < 2; rh++) {
            int o = g * 32 + m * 16 + rh * 8 + qrow;
#pragma unroll
            for (int t = 0; t < 4; t++) {
#pragma unroll
                for (int j = 0; j < 2; j++) {
                    int p = px0 + t * 8 + qcol * 2 + j;
                    float yv = yb[(size_t)o * PY_ + si[p]];
                    float xfv = acc[m][t][rh * 2 + j] * zs[p] + yv * zs[64 + p];
                    trans[p * T_PITCH + o] = xfv;
                }
            }
        }
    }
    __syncthreads();

    {
        int p = tid >> 3, c0 = (tid & 7) * 32;
        float* dst = g_nhwc + ((size_t)n * P_ + p0 + p) * 256 + c0;
        const float* src = trans + p * T_PITCH + c0;
#pragma unroll
        for (int u = 0; u < 8; u++)
            *(float4*)(dst + u * 4) = *(const float4*)(src + u * 4);
    }
    {
        int o = tid >> 1, half = tid & 1;
        float* dst = xf_nchw + ((size_t)(n * 256 + o)) * P_ + p0 + half * 32;
#pragma unroll
        for (int u = 0; u < 8; u++) {
            float4 v;
            v.x = trans[(half * 32 + u * 4 + 0) * T_PITCH + o];
            v.y = trans[(half * 32 + u * 4 + 1) * T_PITCH + o];
            v.z = trans[(half * 32 + u * 4 + 2) * T_PITCH + o];
            v.w = trans[(half * 32 + u * 4 + 3) * T_PITCH + o];
            *(float4*)(dst + u * 4) = v;
        }
    }
}

// ---------------------------------------------------------------------------
// Kernel 2: offset conv3x3 via mma.sync tf32.
// Block = one image row (56 px, pad 64), 256 thr / 8 warps; grid (56, 8).
// M = 18 padded to 32; K = 2304 in 72 chunks (tap kk, 32 ch).
// B from NHWC xf with integer tap shifts (borders -> 0). Same pipeline as k3.
// ---------------------------------------------------------------------------
__global__ __launch_bounds__(256)
void k2_mma()
{
    __shared__ float sa[3 * 1024];
    __shared__ float sb[2 * 2560];
    const uint32_t sAu = smem_u32(sa);

    const int h = blockIdx.x, n = blockIdx.y;
    const int tid = threadIdx.x, wid = tid >> 5, lane = tid & 31;
    const int qrow = lane >> 2, qcol = lane & 3;

    const float* nh = g_nhwc + (size_t)n * P_ * 256;
    const int fp = tid >> 2;          // pixel 0..63
    const int cg = (tid & 3) * 8;     // channel group base (0,8,16,24)

    float acc[2][4];
#pragma unroll
    for (int m = 0; m < 2; m++)
#pragma unroll
        for (int c = 0; c < 4; c++) acc[m][c] = 0.f;

    float st0[8], st1[8];

    auto a_issue = [&](int slot, int ch) {
        cp_async16(sAu + (uint32_t)(slot * 1024 + tid * 4) * 4,
                   g_w2t + (size_t)ch * 1024 + tid * 4);
        CP_COMMIT();
    };
    auto b_issue = [&](float* st, int ch) {
        int kk = ch >> 3, c0 = (ch & 7) * 32;
        int dy = kk / 3 - 1, dx = kk % 3 - 1;
        int row = h + dy, xx = fp + dx;
        bool valid = (row >= 0) && (row < 56) && (xx >= 0) && (xx < 56) && (fp < 56);
        if (valid) {
            const float* src = nh + ((size_t)(row * 56 + xx)) * 256 + c0 + cg;
            *(float4*)(st)     = *(const float4*)(src);
            *(float4*)(st + 4) = *(const float4*)(src + 4);
        } else {
#pragma unroll
            for (int i = 0; i < 8; i++) st[i] = 0.f;
        }
    };
    auto b_combine = [&](const float* st, int ch) {
        float* dst = sb + (ch & 1) * 2560 + fp * 40 + cg;
#pragma unroll
        for (int i = 0; i < 8; i++) {
            int sp = (i & 3) * 2 + (i >> 2);
            dst[sp] = to_tf32(st[i]);
        }
    };
    auto do_mma = [&](int ch) {
        const float* Ab = sa + (ch % 3) * 1024;
        const float* Sb2 = sb + (ch & 1) * 2560;
#pragma unroll
        for (int s = 0; s < 4; s++) {
            float4 av0 = *(const float4*)(Ab + s * 256 + lane * 4);
            float4 av1 = *(const float4*)(Ab + s * 256 + 128 + lane * 4);
            float2 bv = *(const float2*)(Sb2 + (wid * 8 + qrow) * 40 + s * 8 + qcol * 2);
            mma_tf32(acc[0], (const uint32_t*)&av0, (const uint32_t*)&bv);
            mma_tf32(acc[1], (const uint32_t*)&av1, (const uint32_t*)&bv);
        }
    };

    a_issue(0, 0);
    a_issue(1, 1);
    b_issue(st0, 0);
    b_issue(st1, 1);
    b_combine(st0, 0);
    CP_WAIT1();
    __syncthreads();

    auto iter = [&](int ch, float* stCur, float* stOther) {
        bool more2 = (ch + 2 < 72);
        if (more2) {
            a_issue((ch + 2) % 3, ch + 2);
            b_issue(stCur, ch + 2);
        }
        if (ch + 1 < 72) b_combine(stOther, ch + 1);
        do_mma(ch);
        if (more2) { CP_WAIT1(); }
        else if (ch + 1 < 72) { CP_WAIT0(); }
        __syncthreads();
    };
    for (int c2 = 0; c2 < 72; c2 += 2) {
        iter(c2,     st0, st1);
        iter(c2 + 1, st1, st0);
    }

    // store: o < 18, px < 56
#pragma unroll
    for (int m = 0; m < 2; m++) {
#pragma unroll
        for (int rh = 0; rh < 2; rh++) {
            int o = m * 16 + rh * 8 + qrow;
            int px = wid * 8 + qcol * 2;
            if (o < 18 && px < 56) {
                float* ob = g_off + ((size_t)(n * 18 + o)) * P_ + h * 56 + px;
                ob[0] = acc[m][rh * 2 + 0];
                ob[1] = acc[m][rh * 2 + 1];
            }
        }
    }
}

// ---------------------------------------------------------------------------
// Kernel 3: deformable conv via mma.sync tf32, deep pipeline. (unchanged R7)
// ---------------------------------------------------------------------------
#define WCHUNK 8192
#define SCHUNK 2560
#define OFS_W   0
#define OFS_S   (OFS_W + 3 * WCHUNK)
#define OFS_MW  (OFS_S + 2 * SCHUNK)
#define OFS_MO  (OFS_MW + 2304)
#define S3_FLOATS (OFS_MO + 2304)

__global__ __launch_bounds__(512, 1)
void k3_mma(const float* __restrict__ g2, const float* __restrict__ b2,
            const float* __restrict__ mu2, const float* __restrict__ v2,
            float* __restrict__ out)
{
    extern __shared__ float smf[];
    float*  wbuf = smf + OFS_W;
    float*  sbuf = smf + OFS_S;
    float4* mw4  = (float4*)(smf + OFS_MW);
    int4*   mo4  = (int4*)(smf + OFS_MO);
    const uint32_t sW = smem_u32(smf + OFS_W);

    const int n   = blockIdx.y;
    const int p0  = blockIdx.x * 64;
    const int tid = threadIdx.x;
    const int wid = tid >> 5;
    const int lane = tid & 31;

    for (int e = tid; e < 576; e += 512) {
        int p = e / 9, k = e - p * 9;
        int pg = p0 + p;
        int ph = pg / 56, pw = pg % 56;
        float dy = g_off[((size_t)(n * 18 + 2 * k)) * P_ + pg];
        float dx = g_off[((size_t)(n * 18 + 2 * k + 1)) * P_ + pg];
        float sy = (float)(ph - 1 + k / 3) + dy;
        float sx = (float)(pw - 1 + k % 3) + dx;
        float y0f = floorf(sy), x0f = floorf(sx);
        float wy1 = sy - y0f, wx1 = sx - x0f;
        int iy0 = (int)y0f, ix0 = (int)x0f;
        bool vy0 = (iy0 >= 0) && (iy0 <= 55);
        bool vy1 = (iy0 + 1 >= 0) && (iy0 + 1 <= 55);
        bool vx0 = (ix0 >= 0) && (ix0 <= 55);
        bool vx1 = (ix0 + 1 >= 0) && (ix0 + 1 <= 55);
        int y0c = min(max(iy0, 0), 55),     y1c = min(max(iy0 + 1, 0), 55);
        int x0c = min(max(ix0, 0), 55),     x1c = min(max(ix0 + 1, 0), 55);
        float4 w;
        w.x = (vy0 && vx0) ? (1.f - wy1) * (1.f - wx1) : 0.f;
        w.y = (vy0 && vx1) ? (1.f - wy1) * wx1 : 0.f;
        w.z = (vy1 && vx0) ? wy1 * (1.f - wx1) : 0.f;
        w.w = (vy1 && vx1) ? wy1 * wx1 : 0.f;
        int4 oo;
        oo.x = (y0c * 56 + x0c) * 256;
        oo.y = (y0c * 56 + x1c) * 256;
        oo.z = (y1c * 56 + x0c) * 256;
        oo.w = (y1c * 56 + x1c) * 256;
        mw4[e] = w;
        mo4[e] = oo;
    }
    __syncthreads();

    const float* nh = g_nhwc + (size_t)n * P_ * 256;
    const int g    = wid >> 1;
    const int px0  = (wid & 1) * 32;
    const int qrow = lane >> 2;
    const int qcol = lane & 3;
    const int spos = (lane >> 3) * 8 + (lane & 3) * 2 + ((lane & 7) >> 2);

    float acc[2][4][4];
#pragma unroll
    for (int m = 0; m < 2; m++)
#pragma unroll
        for (int t = 0; t < 4; t++)
#pragma unroll
            for (int c = 0; c < 4; c++) acc[m][t][c] = 0.f;

    float st0[16], st1[16];

    auto weights_issue = [&](int slot, int ch) {
#pragma unroll
        for (int gl = 0; gl < 4; gl++) {
            int f = (gl * 512 + tid) * 4;
            int og = f >> 10, inner = f & 1023;
            const float* src = g_wt + ((size_t)og * 72 + ch) * 1024 + inner;
            cp_async16(sW + (slot * WCHUNK + f) * 4, src);
        }
        CP_COMMIT();
    };
    auto gather_issue = [&](float* st, int ch) {
        const int kk = ch >> 3;
        const int ci = ((ch & 7) * 32) + lane;
#pragma unroll
        for (int i = 0; i < 4; i++) {
            int p = wid * 4 + i;
            int4 oo = mo4[p * 9 + kk];
            st[i*4+0] = nh[oo.x + ci];
            st[i*4+1] = nh[oo.y + ci];
            st[i*4+2] = nh[oo.z + ci];
            st[i*4+3] = nh[oo.w + ci];
        }
    };
    auto combine = [&](const float* st, int ch) {
        const int kk = ch >> 3;
        float* dst = sbuf + (ch & 1) * SCHUNK;
#pragma unroll
        for (int i = 0; i < 4; i++) {
            int p = wid * 4 + i;
            float4 w = mw4[p * 9 + kk];
            float v = w.x * st[i*4+0] + w.y * st[i*4+1]
                    + w.z * st[i*4+2] + w.w * st[i*4+3];
            dst[p * 40 + spos] = to_tf32(v);
        }
    };
    auto do_mma = [&](int ch) {
        const float* Ab = wbuf + (ch % 3) * WCHUNK + g * 1024;
        const float* Sb = sbuf + (ch & 1) * SCHUNK;
#pragma unroll
        for (int s = 0; s < 4; s++) {
            float4 av[2];
#pragma unroll
            for (int m = 0; m < 2; m++)
                av[m] = *(const float4*)(Ab + s * 256 + m * 128 + lane * 4);
            float2 bv[4];
            const float* sr = Sb + (px0 + qrow) * 40 + s * 8 + qcol * 2;
#pragma unroll
            for (int t = 0; t < 4; t++)
                bv[t] = *(const float2*)(sr + t * 8 * 40);
#pragma unroll
            for (int m = 0; m < 2; m++)
#pragma unroll
                for (int t = 0; t < 4; t++)
                    mma_tf32(acc[m][t], (const uint32_t*)&av[m], (const uint32_t*)&bv[t]);
        }
    };

    weights_issue(0, 0);
    weights_issue(1, 1);
    gather_issue(st0, 0);
    gather_issue(st1, 1);
    combine(st0, 0);
    CP_WAIT1();
    __syncthreads();

    auto iter = [&](int ch, float* stCur, float* stOther) {
        bool more2 = (ch + 2 < 72);
        if (more2) {
            weights_issue((ch + 2) % 3, ch + 2);
            gather_issue(stCur, ch + 2);
        }
        if (ch + 1 < 72) combine(stOther, ch + 1);
        do_mma(ch);
        if (more2) { CP_WAIT1(); }
        else if (ch + 1 < 72) { CP_WAIT0(); }
        __syncthreads();
    };
    for (int c2 = 0; c2 < 72; c2 += 2) {
        iter(c2,     st0, st1);
        iter(c2 + 1, st1, st0);
    }

#pragma unroll
    for (int m = 0; m < 2; m++) {
#pragma unroll
        for (int rh = 0; rh < 2; rh++) {
            int o = g * 32 + m * 16 + rh * 8 + qrow;
            float sc = g2[o] * rsqrtf(v2[o] + EPSF);
            float bi = b2[o] - mu2[o] * sc;
            float* ob = out + ((size_t)(n * 256 + o)) * P_ + p0 + px0;
#pragma unroll
            for (int t = 0; t < 4; t++) {
                float2 v;
                v.x = fmaf(acc[m][t][rh * 2 + 0], sc, bi);
                v.y = fmaf(acc[m][t][rh * 2 + 1], sc, bi);
                *(float2*)(ob + t * 8 + 2 * qcol) = v;
            }
        }
    }
}

// ---------------------------------------------------------------------------
extern "C" void kernel_launch(void* const* d_in, const int* in_sizes, int n_in,
                              void* d_out, int out_size)
{
    const float* x       = (const float*)d_in[0];
    const float* y       = (const float*)d_in[1];
    const float* conv1_w = (const float*)d_in[2];
    const float* bn1_g   = (const float*)d_in[3];
    const float* bn1_b   = (const float*)d_in[4];
    const float* bn1_m   = (const float*)d_in[5];
    const float* bn1_v   = (const float*)d_in[6];
    const float* att_w   = (const float*)d_in[7];
    const float* att_b   = (const float*)d_in[8];
    const float* off_w   = (const float*)d_in[9];
    const float* dcn_w   = (const float*)d_in[10];
    const float* bn2_g   = (const float*)d_in[11];
    const float* bn2_b   = (const float*)d_in[12];
    const float* bn2_m   = (const float*)d_in[13];
    const float* bn2_v   = (const float*)d_in[14];

    float* out = (float*)d_out;
    const size_t one = (size_t)N_ * OUTC * P_;  // 6,422,528

    float* xf_nchw;
    if ((size_t)out_size >= 2 * one) {
        xf_nchw = out + one;  // tuple (out, xf) flattened
    } else {
        void* p = nullptr;
        cudaGetSymbolAddress(&p, g_xf_scratch);
        xf_nchw = (float*)p;
    }

    cudaFuncSetAttribute(k1_mma, cudaFuncAttributeMaxDynamicSharedMemorySize, 140 * 1024);
    cudaFuncSetAttribute(k3_mma, cudaFuncAttributeMaxDynamicSharedMemorySize, 144 * 1024);

    k0_wt<<<576, 256>>>(dcn_w);
    k0_w1<<<128, 256>>>(conv1_w);
    k0_w2<<<72, 256>>>(off_w);

    k1_mma<<<dim3(49, 8), 512, K1_FLOATS * 4>>>(x, y, bn1_g, bn1_b, bn1_m, bn1_v,
                                                att_w, att_b, xf_nchw);

    k2_mma<<<dim3(56, 8), 256>>>();

    k3_mma<<<dim3(49, 8), 512, S3_FLOATS * 4>>>(bn2_g, bn2_b, bn2_m, bn2_v, out);
}

// round 10
// speedup vs baseline: 2.4005x; 1.2726x over previous
#include <cuda_runtime.h>
#include <cuda_fp16.h>
#include <math.h>
#include <stdint.h>

#define N_   8
#define CIN  512
#define MID  256
#define OUTC 256
#define H_   56
#define W_   56
#define P_   3136
#define PY_  784
#define EPSF 1e-5f

// Scratch (static device globals; no allocation allowed)
__device__ float  g_nhwc[(size_t)N_ * P_ * MID];       // xf in NHWC for gather
__device__ float  g_off[(size_t)N_ * 18 * P_];         // offsets
__device__ float  g_xf_scratch[(size_t)N_ * MID * P_]; // xf NCHW fallback
__device__ __half g_wth[(size_t)OUTC * 2304];          // dcn weights fp16 fragment-major
__device__ float  g_w1t[(size_t)MID * CIN];            // conv1 weights tf32 fragment-major
__device__ __half g_w2th[(size_t)72 * 1024];           // offset-conv weights fp16 (M pad 32)

// ---------------------------------------------------------------------------
// helpers (family-safe PTX only: sm_80+ instructions)
// ---------------------------------------------------------------------------
__device__ __forceinline__ float to_tf32(float x) {
    uint32_t u;
    asm("cvt.rna.tf32.f32 %0, %1;" : "=r"(u) : "f"(x));
    return __uint_as_float(u);
}
__device__ __forceinline__ uint32_t to_tf32u(float x) {
    uint32_t u;
    asm("cvt.rna.tf32.f32 %0, %1;" : "=r"(u) : "f"(x));
    return u;
}
__device__ __forceinline__ void mma_tf32(float* d, const uint32_t* a, const uint32_t* b) {
    asm volatile(
        "mma.sync.aligned.m16n8k8.row.col.f32.tf32.tf32.f32 "
        "{%0,%1,%2,%3}, {%4,%5,%6,%7}, {%8,%9}, {%0,%1,%2,%3};"
        : "+f"(d[0]), "+f"(d[1]), "+f"(d[2]), "+f"(d[3])
        : "r"(a[0]), "r"(a[1]), "r"(a[2]), "r"(a[3]), "r"(b[0]), "r"(b[1]));
}
__device__ __forceinline__ void mma_fp16(float* d, const uint32_t* a, const uint32_t* b) {
    asm volatile(
        "mma.sync.aligned.m16n8k16.row.col.f32.f16.f16.f32 "
        "{%0,%1,%2,%3}, {%4,%5,%6,%7}, {%8,%9}, {%0,%1,%2,%3};"
        : "+f"(d[0]), "+f"(d[1]), "+f"(d[2]), "+f"(d[3])
        : "r"(a[0]), "r"(a[1]), "r"(a[2]), "r"(a[3]), "r"(b[0]), "r"(b[1]));
}
__device__ __forceinline__ uint32_t smem_u32(const void* p) {
    uint32_t a;
    asm("{ .reg .u64 t; cvta.to.shared.u64 t, %1; cvt.u32.u64 %0, t; }" : "=r"(a) : "l"(p));
    return a;
}
__device__ __forceinline__ void cp_async16(uint32_t dst, const void* src) {
    asm volatile("cp.async.cg.shared.global [%0], [%1], 16;" :: "r"(dst), "l"(src));
}
#define CP_COMMIT() asm volatile("cp.async.commit_group;" ::: "memory")
#define CP_WAIT0()  asm volatile("cp.async.wait_group 0;" ::: "memory")
#define CP_WAIT1()  asm volatile("cp.async.wait_group 1;" ::: "memory")

// fp16 m16n8k16 fragment-major index helpers:
// per (s,m) tile: 32 lanes x 8 halves; j=0,1->a0 (o=r,k=q*2+j), j=2,3->a1(o=r+8),
// j=4,5->a2(k+8), j=6,7->a3(o+8,k+8)
// B smem pairing: sp(k) = ((k>>1)&3)*4 + ((k>>3)&1)*2 + (k&1) + (k>>4)*16

// ---------------------------------------------------------------------------
// Kernel 0a: dcn weights -> fp16 fragment-major (72 chunks of (tap kk, 32c))
// ---------------------------------------------------------------------------
__global__ void k0_wth(const float* __restrict__ dw)
{
    const int og = blockIdx.x / 72, ch = blockIdx.x % 72;
    const int kk = ch >> 3, c0 = (ch & 7) * 32;
    for (int t = threadIdx.x; t < 1024; t += 256) {
        int j = t & 7, lane = (t >> 3) & 31, m = (t >> 8) & 1, s = t >> 9;
        int r = lane >> 2, q = lane & 3;
        int o = og * 32 + m * 16 + r + ((j >> 1) & 1) * 8;
        int kl = s * 16 + (j >> 2) * 8 + q * 2 + (j & 1);
        int c = c0 + kl;
        g_wth[(size_t)blockIdx.x * 1024 + t] =
            __float2half_rn(dw[(size_t)o * 2304 + c * 9 + kk]);
    }
}

// ---------------------------------------------------------------------------
// Kernel 0b: conv1 weights -> tf32 fragment-major (16 chunks of 32c) (unchanged)
// ---------------------------------------------------------------------------
__global__ void k0_w1(const float* __restrict__ w1)
{
    const int og = blockIdx.x >> 4, ch = blockIdx.x & 15;
    for (int t = threadIdx.x; t < 1024; t += 256) {
        int j = t & 3, lane = (t >> 2) & 31, m = (t >> 7) & 1, s = (t >> 8) & 3;
        int o = og * 32 + m * 16 + (lane >> 2) + (j & 1) * 8;
        int c = ch * 32 + s * 8 + (lane & 3) + (j >> 1) * 4;
        g_w1t[(size_t)blockIdx.x * 1024 + t] = to_tf32(w1[(size_t)o * 512 + c]);
    }
}

// ---------------------------------------------------------------------------
// Kernel 0c: offset-conv weights (18 pad 32) -> fp16 fragment-major
// ---------------------------------------------------------------------------
__global__ void k0_w2h(const float* __restrict__ ow)
{
    const int ch = blockIdx.x;
    const int kk = ch >> 3, c0 = (ch & 7) * 32;
    for (int t = threadIdx.x; t < 1024; t += 256) {
        int j = t & 7, lane = (t >> 3) & 31, m = (t >> 8) & 1, s = t >> 9;
        int r = lane >> 2, q = lane & 3;
        int o = m * 16 + r + ((j >> 1) & 1) * 8;
        int kl = s * 16 + (j >> 2) * 8 + q * 2 + (j & 1);
        int c = c0 + kl;
        float v = (o < 18) ? ow[(size_t)o * 2304 + c * 9 + kk] : 0.f;
        g_w2th[(size_t)ch * 1024 + t] = __float2half_rn(v);
    }
}

// ---------------------------------------------------------------------------
// Kernel 1: conv1 via mma.sync tf32 + BN1 + upsample + attention fuse (R8)
// ---------------------------------------------------------------------------
#define X_PITCH 72
#define XCHUNK (32 * X_PITCH)
#define K1_WCHUNK 8192
#define K1_OFS_W   0
#define K1_OFS_X   (K1_OFS_W + 3 * K1_WCHUNK)
#define K1_OFS_AW  (K1_OFS_X + 3 * XCHUNK)
#define K1_OFS_RED (K1_OFS_AW + 1024)
#define K1_OFS_ZS  (K1_OFS_RED + 1024)
#define K1_OFS_SI  (K1_OFS_ZS + 128)
#define K1_FLOATS  (K1_OFS_SI + 64)
#define T_PITCH 260

__global__ __launch_bounds__(512, 1)
void k1_mma(const float* __restrict__ x, const float* __restrict__ y,
            const float* __restrict__ g1, const float* __restrict__ b1,
            const float* __restrict__ mu1, const float* __restrict__ v1,
            const float* __restrict__ attw, const float* __restrict__ attb,
            float* __restrict__ xf_nchw)
{
    extern __shared__ float smf[];
    float* wbuf = smf + K1_OFS_W;
    float* xbuf = smf + K1_OFS_X;
    float* aw   = smf + K1_OFS_AW;
    float* red  = smf + K1_OFS_RED;
    float* zs   = smf + K1_OFS_ZS;
    int*   si   = (int*)(smf + K1_OFS_SI);
    const uint32_t sB = smem_u32(smf);

    const int n   = blockIdx.y;
    const int p0  = blockIdx.x * 64;
    const int tid = threadIdx.x;
    const int wid = tid >> 5;
    const int lane = tid & 31;

    for (int i = tid; i < 1024; i += 512) aw[i] = attw[i];
    if (tid < 64) {
        int pg = p0 + tid;
        int hh = pg / 56, ww = pg % 56;
        si[tid] = (hh >> 1) * 28 + (ww >> 1);
    }

    const float* xb = x + (size_t)n * CIN * P_;
    const int xc  = tid >> 4, xseg = tid & 15;

    auto wi = [&](int slot, int ch) {
#pragma unroll
        for (int gl = 0; gl < 4; gl++) {
            int f = (gl * 512 + tid) * 4;
            int og = f >> 10, inner = f & 1023;
            cp_async16(sB + (uint32_t)(K1_OFS_W + slot * K1_WCHUNK + f) * 4,
                       g_w1t + ((size_t)og * 16 + ch) * 1024 + inner);
        }
    };
    auto xi = [&](int slot, int ch) {
        cp_async16(sB + (uint32_t)(K1_OFS_X + slot * XCHUNK + xc * X_PITCH + xseg * 4) * 4,
                   xb + (size_t)(ch * 32 + xc) * P_ + p0 + xseg * 4);
    };

    float acc[2][4][4];
#pragma unroll
    for (int m = 0; m < 2; m++)
#pragma unroll
        for (int t = 0; t < 4; t++)
#pragma unroll
            for (int c = 0; c < 4; c++) acc[m][t][c] = 0.f;

    wi(0, 0); xi(0, 0); CP_COMMIT();
    wi(1, 1); xi(1, 1); CP_COMMIT();
    CP_WAIT1();
    __syncthreads();

    const int g    = wid >> 1;
    const int px0  = (wid & 1) * 32;
    const int qrow = lane >> 2;
    const int qcol = lane & 3;

    for (int ch = 0; ch < 16; ch++) {
        int slot = ch % 3;
        bool more2 = (ch + 2 < 16);
        if (more2) { wi((ch + 2) % 3, ch + 2); xi((ch + 2) % 3, ch + 2); CP_COMMIT(); }
        const float* Ab = wbuf + slot * K1_WCHUNK + g * 1024;
        const float* Xc = xbuf + slot * XCHUNK;
#pragma unroll
        for (int s = 0; s < 4; s++) {
            float4 av[2];
#pragma unroll
            for (int m = 0; m < 2; m++)
                av[m] = *(const float4*)(Ab + s * 256 + m * 128 + lane * 4);
            uint32_t bb[4][2];
            const float* xr0 = Xc + (s * 8 + qcol) * X_PITCH + px0 + qrow;
            const float* xr1 = xr0 + 4 * X_PITCH;
#pragma unroll
            for (int t = 0; t < 4; t++) {
                bb[t][0] = to_tf32u(xr0[t * 8]);
                bb[t][1] = to_tf32u(xr1[t * 8]);
            }
#pragma unroll
            for (int m = 0; m < 2; m++)
#pragma unroll
                for (int t = 0; t < 4; t++)
                    mma_tf32(acc[m][t], (const uint32_t*)&av[m], bb[t]);
        }
        if (more2) { CP_WAIT1(); }
        else if (ch + 1 < 16) { CP_WAIT0(); }
        __syncthreads();
    }

    const float* yb = y + (size_t)n * MID * PY_;
    float t0p[8], t1p[8];
#pragma unroll
    for (int pj = 0; pj < 8; pj++) { t0p[pj] = 0.f; t1p[pj] = 0.f; }

#pragma unroll
    for (int m = 0; m < 2; m++) {
#pragma unroll
        for (int rh = 0; rh < 2; rh++) {
            int o = g * 32 + m * 16 + rh * 8 + qrow;
            float sc = g1[o] * rsqrtf(v1[o] + EPSF);
            float bi = b1[o] - mu1[o] * sc;
            float axm0 = aw[o], ayu0 = aw[256 + o];
            float axm1 = aw[512 + o], ayu1 = aw[768 + o];
#pragma unroll
            for (int t = 0; t < 4; t++) {
#pragma unroll
                for (int j = 0; j < 2; j++) {
                    int pj = t * 2 + j;
                    int p = px0 + t * 8 + qcol * 2 + j;
                    float xv = fmaf(acc[m][t][rh * 2 + j], sc, bi);
                    acc[m][t][rh * 2 + j] = xv;
                    float yv = yb[(size_t)o * PY_ + si[p]];
                    t0p[pj] = fmaf(axm0, xv, fmaf(ayu0, yv, t0p[pj]));
                    t1p[pj] = fmaf(axm1, xv, fmaf(ayu1, yv, t1p[pj]));
                }
            }
        }
    }
#pragma unroll
    for (int pj = 0; pj < 8; pj++) {
#pragma unroll
        for (int off = 4; off < 32; off <<= 1) {
            t0p[pj] += __shfl_xor_sync(0xffffffffu, t0p[pj], off);
            t1p[pj] += __shfl_xor_sync(0xffffffffu, t1p[pj], off);
        }
    }
    if (qrow == 0) {
#pragma unroll
        for (int t = 0; t < 4; t++)
#pragma unroll
            for (int j = 0; j < 2; j++) {
                int p = px0 + t * 8 + qcol * 2 + j;
                red[g * 64 + p]       = t0p[t * 2 + j];
                red[512 + g * 64 + p] = t1p[t * 2 + j];
            }
    }
    __syncthreads();
    if (tid < 128) {
        int which = tid & 1, p = tid >> 1;
        float s = 0.f;
#pragma unroll
        for (int gg = 0; gg < 8; gg++) s += red[which * 512 + gg * 64 + p];
        zs[which * 64 + p] = 1.f / (1.f + expf(-(s + attb[which])));
    }
    __syncthreads();

    float* trans = wbuf;
#pragma unroll
    for (int m = 0; m < 2; m++) {
#pragma unroll
        for (int rh = 0; rh < 2; rh++) {
            int o = g * 32 + m * 16 + rh * 8 + qrow;
#pragma unroll
            for (int t = 0; t < 4; t++) {
#pragma unroll
                for (int j = 0; j < 2; j++) {
                    int p = px0 + t * 8 + qcol * 2 + j;
                    float yv = yb[(size_t)o * PY_ + si[p]];
                    float xfv = acc[m][t][rh * 2 + j] * zs[p] + yv * zs[64 + p];
                    trans[p * T_PITCH + o] = xfv;
                }
            }
        }
    }
    __syncthreads();

    {
        int p = tid >> 3, c0 = (tid & 7) * 32;
        float* dst = g_nhwc + ((size_t)n * P_ + p0 + p) * 256 + c0;
        const float* src = trans + p * T_PITCH + c0;
#pragma unroll
        for (int u = 0; u < 8; u++)
            *(float4*)(dst + u * 4) = *(const float4*)(src + u * 4);
    }
    {
        int o = tid >> 1, half = tid & 1;
        float* dst = xf_nchw + ((size_t)(n * 256 + o)) * P_ + p0 + half * 32;
#pragma unroll
        for (int u = 0; u < 8; u++) {
            float4 v;
            v.x = trans[(half * 32 + u * 4 + 0) * T_PITCH + o];
            v.y = trans[(half * 32 + u * 4 + 1) * T_PITCH + o];
            v.z = trans[(half * 32 + u * 4 + 2) * T_PITCH + o];
            v.w = trans[(half * 32 + u * 4 + 3) * T_PITCH + o];
            *(float4*)(dst + u * 4) = v;
        }
    }
}

// ---------------------------------------------------------------------------
// Kernel 2: offset conv3x3 via mma.sync fp16. 2 rows/block, 512 thr, grid (28,8).
// M = 18 pad 32; K = 2304 in 72 chunks (tap kk, 32 ch). N = 128 (2x56 + pad).
// ---------------------------------------------------------------------------
__global__ __launch_bounds__(512)
void k2_mma()
{
    __shared__ __half sa[3 * 1024];
    __shared__ __half sb[2 * 5120];   // 128 px x pitch 40 halves
    const uint32_t sAu = smem_u32(sa);

    const int h2 = blockIdx.x, n = blockIdx.y;
    const int tid = threadIdx.x, wid = tid >> 5, lane = tid & 31;
    const int qrow = lane >> 2, qcol = lane & 3;

    const float* nh = g_nhwc + (size_t)n * P_ * 256;
    const int fp = tid >> 2;          // pixel 0..127
    const int cg = (tid & 3) * 8;     // channel group base
    const int rowl = fp >> 6, colf = fp & 63;
    const int base_sp = (cg >> 4) * 16 + ((cg >> 3) & 1) * 2;

    float acc[2][4];
#pragma unroll
    for (int m = 0; m < 2; m++)
#pragma unroll
        for (int c = 0; c < 4; c++) acc[m][c] = 0.f;

    float st0[8], st1[8];

    auto a_issue = [&](int slot, int ch) {
        if (tid < 128)
            cp_async16(sAu + (uint32_t)(slot * 1024 + tid * 8) * 2,
                       g_w2th + (size_t)ch * 1024 + tid * 8);
        CP_COMMIT();
    };
    auto b_issue = [&](float* st, int ch) {
        int kk = ch >> 3, c0 = (ch & 7) * 32;
        int dy = kk / 3 - 1, dx = kk % 3 - 1;
        int rr = h2 * 2 + rowl + dy, xx = colf + dx;
        bool valid = (rr >= 0) && (rr < 56) && (xx >= 0) && (xx < 56) && (colf < 56);
        if (valid) {
            const float* src = nh + ((size_t)(rr * 56 + xx)) * 256 + c0 + cg;
            *(float4*)(st)     = *(const float4*)(src);
            *(float4*)(st + 4) = *(const float4*)(src + 4);
        } else {
#pragma unroll
            for (int i = 0; i < 8; i++) st[i] = 0.f;
        }
    };
    auto b_combine = [&](const float* st, int ch) {
        __half* dst = sb + (ch & 1) * 5120 + fp * 40;
#pragma unroll
        for (int i = 0; i < 4; i++) {
            __half2 hv = __floats2half2_rn(st[2 * i], st[2 * i + 1]);
            *(__half2*)(dst + base_sp + i * 4) = hv;
        }
    };
    auto do_mma = [&](int ch) {
        const __half* Ab = sa + (ch % 3) * 1024;
        const __half* Sb2 = sb + (ch & 1) * 5120;
#pragma unroll
        for (int s = 0; s < 2; s++) {
            uint4 av0 = *(const uint4*)(Ab + s * 512 + lane * 8);
            uint4 av1 = *(const uint4*)(Ab + s * 512 + 256 + lane * 8);
            uint2 bv = *(const uint2*)(Sb2 + (wid * 8 + qrow) * 40 + s * 16 + qcol * 4);
            mma_fp16(acc[0], (const uint32_t*)&av0, (const uint32_t*)&bv);
            mma_fp16(acc[1], (const uint32_t*)&av1, (const uint32_t*)&bv);
        }
    };

    a_issue(0, 0);
    a_issue(1, 1);
    b_issue(st0, 0);
    b_issue(st1, 1);
    b_combine(st0, 0);
    CP_WAIT1();
    __syncthreads();

    auto iter = [&](int ch, float* stCur, float* stOther) {
        bool more2 = (ch + 2 < 72);
        if (more2) {
            a_issue((ch + 2) % 3, ch + 2);
            b_issue(stCur, ch + 2);
        }
        if (ch + 1 < 72) b_combine(stOther, ch + 1);
        do_mma(ch);
        if (more2) { CP_WAIT1(); }
        else if (ch + 1 < 72) { CP_WAIT0(); }
        __syncthreads();
    };
    for (int c2 = 0; c2 < 72; c2 += 2) {
        iter(c2,     st0, st1);
        iter(c2 + 1, st1, st0);
    }

#pragma unroll
    for (int m = 0; m < 2; m++) {
#pragma unroll
        for (int rh = 0; rh < 2; rh++) {
            int o = m * 16 + rh * 8 + qrow;
            int px = wid * 8 + qcol * 2;
            int rr = h2 * 2 + (px >> 6), col = px & 63;
            if (o < 18 && col < 56) {
                float* ob = g_off + ((size_t)(n * 18 + o)) * P_ + rr * 56 + col;
                ob[0] = acc[m][rh * 2 + 0];
                ob[1] = acc[m][rh * 2 + 1];
            }
        }
    }
}

// ---------------------------------------------------------------------------
// Kernel 3: deformable conv via mma.sync fp16, deep pipeline.
// 512 threads, tile 256 o x 64 px; grid (49, 8). 72 chunks (tap kk, 32 ch).
// ---------------------------------------------------------------------------
#define K3_WCH 8192   // halves per weight chunk
#define K3_SCH 2560   // halves per S buffer (64 px x pitch 40)
#define K3_OFS_W   0                          // 3 x 16384 B = 49152
#define K3_OFS_S   49152                      // 2 x 5120 B  = 10240
#define K3_OFS_MW  59392                      // 9216
#define K3_OFS_MO  68608                      // 9216
#define K3_BYTES   77824

__global__ __launch_bounds__(512, 1)
void k3_mma(const float* __restrict__ g2, const float* __restrict__ b2,
            const float* __restrict__ mu2, const float* __restrict__ v2,
            float* __restrict__ out)
{
    extern __shared__ char smc[];
    __half* wbuf = (__half*)(smc + K3_OFS_W);
    __half* sbuf = (__half*)(smc + K3_OFS_S);
    float4* mw4  = (float4*)(smc + K3_OFS_MW);
    int4*   mo4  = (int4*)(smc + K3_OFS_MO);
    const uint32_t sW = smem_u32(smc);

    const int n   = blockIdx.y;
    const int p0  = blockIdx.x * 64;
    const int tid = threadIdx.x;
    const int wid = tid >> 5;
    const int lane = tid & 31;

    for (int e = tid; e < 576; e += 512) {
        int p = e / 9, k = e - p * 9;
        int pg = p0 + p;
        int ph = pg / 56, pw = pg % 56;
        float dy = g_off[((size_t)(n * 18 + 2 * k)) * P_ + pg];
        float dx = g_off[((size_t)(n * 18 + 2 * k + 1)) * P_ + pg];
        float sy = (float)(ph - 1 + k / 3) + dy;
        float sx = (float)(pw - 1 + k % 3) + dx;
        float y0f = floorf(sy), x0f = floorf(sx);
        float wy1 = sy - y0f, wx1 = sx - x0f;
        int iy0 = (int)y0f, ix0 = (int)x0f;
        bool vy0 = (iy0 >= 0) && (iy0 <= 55);
        bool vy1 = (iy0 + 1 >= 0) && (iy0 + 1 <= 55);
        bool vx0 = (ix0 >= 0) && (ix0 <= 55);
        bool vx1 = (ix0 + 1 >= 0) && (ix0 + 1 <= 55);
        int y0c = min(max(iy0, 0), 55),     y1c = min(max(iy0 + 1, 0), 55);
        int x0c = min(max(ix0, 0), 55),     x1c = min(max(ix0 + 1, 0), 55);
        float4 w;
        w.x = (vy0 && vx0) ? (1.f - wy1) * (1.f - wx1) : 0.f;
        w.y = (vy0 && vx1) ? (1.f - wy1) * wx1 : 0.f;
        w.z = (vy1 && vx0) ? wy1 * (1.f - wx1) : 0.f;
        w.w = (vy1 && vx1) ? wy1 * wx1 : 0.f;
        int4 oo;
        oo.x = (y0c * 56 + x0c) * 256;
        oo.y = (y0c * 56 + x1c) * 256;
        oo.z = (y1c * 56 + x0c) * 256;
        oo.w = (y1c * 56 + x1c) * 256;
        mw4[e] = w;
        mo4[e] = oo;
    }
    __syncthreads();

    const float* nh = g_nhwc + (size_t)n * P_ * 256;
    const int g    = wid >> 1;
    const int px0  = (wid & 1) * 32;
    const int qrow = lane >> 2;
    const int qcol = lane & 3;
    const int sp = ((lane >> 1) & 3) * 4 + ((lane >> 3) & 1) * 2 + (lane & 1)
                 + (lane >> 4) * 16;

    float acc[2][4][4];
#pragma unroll
    for (int m = 0; m < 2; m++)
#pragma unroll
        for (int t = 0; t < 4; t++)
#pragma unroll
            for (int c = 0; c < 4; c++) acc[m][t][c] = 0.f;

    float st0[16], st1[16];

    auto weights_issue = [&](int slot, int ch) {
#pragma unroll
        for (int gl = 0; gl < 2; gl++) {
            int f = (gl * 512 + tid) * 8;        // half index, 0..8184
            int og = f >> 10, inner = f & 1023;
            cp_async16(sW + (uint32_t)(K3_OFS_W + (slot * K3_WCH + f) * 2),
                       g_wth + ((size_t)og * 72 + ch) * 1024 + inner);
        }
        CP_COMMIT();
    };
    auto gather_issue = [&](float* st, int ch) {
        const int kk = ch >> 3;
        const int ci = ((ch & 7) * 32) + lane;
#pragma unroll
        for (int i = 0; i < 4; i++) {
            int p = wid * 4 + i;
            int4 oo = mo4[p * 9 + kk];
            st[i*4+0] = nh[oo.x + ci];
            st[i*4+1] = nh[oo.y + ci];
            st[i*4+2] = nh[oo.z + ci];
            st[i*4+3] = nh[oo.w + ci];
        }
    };
    auto combine = [&](const float* st, int ch) {
        const int kk = ch >> 3;
        __half* dst = sbuf + (ch & 1) * K3_SCH;
#pragma unroll
        for (int i = 0; i < 4; i++) {
            int p = wid * 4 + i;
            float4 w = mw4[p * 9 + kk];
            float v = w.x * st[i*4+0] + w.y * st[i*4+1]
                    + w.z * st[i*4+2] + w.w * st[i*4+3];
            dst[p * 40 + sp] = __float2half_rn(v);
        }
    };
    auto do_mma = [&](int ch) {
        const __half* Ab = wbuf + (ch % 3) * K3_WCH + g * 1024;
        const __half* Sb = sbuf + (ch & 1) * K3_SCH;
#pragma unroll
        for (int s = 0; s < 2; s++) {
            uint4 av0 = *(const uint4*)(Ab + s * 512 + lane * 8);
            uint4 av1 = *(const uint4*)(Ab + s * 512 + 256 + lane * 8);
            uint2 bv[4];
            const __half* sr = Sb + (px0 + qrow) * 40 + s * 16 + qcol * 4;
#pragma unroll
            for (int t = 0; t < 4; t++)
                bv[t] = *(const uint2*)(sr + t * 8 * 40);
#pragma unroll
            for (int t = 0; t < 4; t++) {
                mma_fp16(acc[0][t], (const uint32_t*)&av0, (const uint32_t*)&bv[t]);
                mma_fp16(acc[1][t], (const uint32_t*)&av1, (const uint32_t*)&bv[t]);
            }
        }
    };

    weights_issue(0, 0);
    weights_issue(1, 1);
    gather_issue(st0, 0);
    gather_issue(st1, 1);
    combine(st0, 0);
    CP_WAIT1();
    __syncthreads();

    auto iter = [&](int ch, float* stCur, float* stOther) {
        bool more2 = (ch + 2 < 72);
        if (more2) {
            weights_issue((ch + 2) % 3, ch + 2);
            gather_issue(stCur, ch + 2);
        }
        if (ch + 1 < 72) combine(stOther, ch + 1);
        do_mma(ch);
        if (more2) { CP_WAIT1(); }
        else if (ch + 1 < 72) { CP_WAIT0(); }
        __syncthreads();
    };
    for (int c2 = 0; c2 < 72; c2 += 2) {
        iter(c2,     st0, st1);
        iter(c2 + 1, st1, st0);
    }

#pragma unroll
    for (int m = 0; m < 2; m++) {
#pragma unroll
        for (int rh = 0; rh < 2; rh++) {
            int o = g * 32 + m * 16 + rh * 8 + qrow;
            float sc = g2[o] * rsqrtf(v2[o] + EPSF);
            float bi = b2[o] - mu2[o] * sc;
            float* ob = out + ((size_t)(n * 256 + o)) * P_ + p0 + px0;
#pragma unroll
            for (int t = 0; t < 4; t++) {
                float2 v;
                v.x = fmaf(acc[m][t][rh * 2 + 0], sc, bi);
                v.y = fmaf(acc[m][t][rh * 2 + 1], sc, bi);
                *(float2*)(ob + t * 8 + 2 * qcol) = v;
            }
        }
    }
}

// ---------------------------------------------------------------------------
extern "C" void kernel_launch(void* const* d_in, const int* in_sizes, int n_in,
                              void* d_out, int out_size)
{
    const float* x       = (const float*)d_in[0];
    const float* y       = (const float*)d_in[1];
    const float* conv1_w = (const float*)d_in[2];
    const float* bn1_g   = (const float*)d_in[3];
    const float* bn1_b   = (const float*)d_in[4];
    const float* bn1_m   = (const float*)d_in[5];
    const float* bn1_v   = (const float*)d_in[6];
    const float* att_w   = (const float*)d_in[7];
    const float* att_b   = (const float*)d_in[8];
    const float* off_w   = (const float*)d_in[9];
    const float* dcn_w   = (const float*)d_in[10];
    const float* bn2_g   = (const float*)d_in[11];
    const float* bn2_b   = (const float*)d_in[12];
    const float* bn2_m   = (const float*)d_in[13];
    const float* bn2_v   = (const float*)d_in[14];

    float* out = (float*)d_out;
    const size_t one = (size_t)N_ * OUTC * P_;  // 6,422,528

    float* xf_nchw;
    if ((size_t)out_size >= 2 * one) {
        xf_nchw = out + one;  // tuple (out, xf) flattened
    } else {
        void* p = nullptr;
        cudaGetSymbolAddress(&p, g_xf_scratch);
        xf_nchw = (float*)p;
    }

    cudaFuncSetAttribute(k1_mma, cudaFuncAttributeMaxDynamicSharedMemorySize, 140 * 1024);
    cudaFuncSetAttribute(k3_mma, cudaFuncAttributeMaxDynamicSharedMemorySize, 80 * 1024);

    k0_wth<<<576, 256>>>(dcn_w);
    k0_w1<<<128, 256>>>(conv1_w);
    k0_w2h<<<72, 256>>>(off_w);

    k1_mma<<<dim3(49, 8), 512, K1_FLOATS * 4>>>(x, y, bn1_g, bn1_b, bn1_m, bn1_v,
                                                att_w, att_b, xf_nchw);

    k2_mma<<<dim3(28, 8), 512>>>();

    k3_mma<<<dim3(49, 8), 512, K3_BYTES>>>(bn2_g, bn2_b, bn2_m, bn2_v, out);
}

// round 11
// speedup vs baseline: 2.4212x; 1.0086x over previous
#include <cuda_runtime.h>
#include <cuda_fp16.h>
#include <math.h>
#include <stdint.h>

#define N_   8
#define CIN  512
#define MID  256
#define OUTC 256
#define H_   56
#define W_   56
#define P_   3136
#define PY_  784
#define EPSF 1e-5f

// Scratch (static device globals; no allocation allowed)
__device__ float  g_nhwc[(size_t)N_ * P_ * MID];       // xf in NHWC for gather
__device__ float  g_off[(size_t)N_ * 18 * P_];         // offsets
__device__ float  g_xf_scratch[(size_t)N_ * MID * P_]; // xf NCHW fallback
__device__ __half g_wth[(size_t)OUTC * 2304];          // dcn weights fp16 fragment-major
__device__ __half g_w1th[(size_t)MID * CIN];           // conv1 weights fp16 fragment-major
__device__ __half g_w2th[(size_t)72 * 1024];           // offset-conv weights fp16 (M pad 32)

// ---------------------------------------------------------------------------
// helpers (family-safe PTX only: sm_80+ instructions)
// ---------------------------------------------------------------------------
__device__ __forceinline__ void mma_fp16(float* d, const uint32_t* a, const uint32_t* b) {
    asm volatile(
        "mma.sync.aligned.m16n8k16.row.col.f32.f16.f16.f32 "
        "{%0,%1,%2,%3}, {%4,%5,%6,%7}, {%8,%9}, {%0,%1,%2,%3};"
        : "+f"(d[0]), "+f"(d[1]), "+f"(d[2]), "+f"(d[3])
        : "r"(a[0]), "r"(a[1]), "r"(a[2]), "r"(a[3]), "r"(b[0]), "r"(b[1]));
}
// pack two f32 into half2 register: {hi=b, lo=a}
__device__ __forceinline__ uint32_t pack_h2(float lo, float hi) {
    uint32_t r;
    asm("cvt.rn.f16x2.f32 %0, %1, %2;" : "=r"(r) : "f"(hi), "f"(lo));
    return r;
}
__device__ __forceinline__ uint32_t smem_u32(const void* p) {
    uint32_t a;
    asm("{ .reg .u64 t; cvta.to.shared.u64 t, %1; cvt.u32.u64 %0, t; }" : "=r"(a) : "l"(p));
    return a;
}
__device__ __forceinline__ void cp_async16(uint32_t dst, const void* src) {
    asm volatile("cp.async.cg.shared.global [%0], [%1], 16;" :: "r"(dst), "l"(src));
}
#define CP_COMMIT() asm volatile("cp.async.commit_group;" ::: "memory")
#define CP_WAIT0()  asm volatile("cp.async.wait_group 0;" ::: "memory")
#define CP_WAIT1()  asm volatile("cp.async.wait_group 1;" ::: "memory")

// ---------------------------------------------------------------------------
// Kernel 0a: dcn weights -> fp16 fragment-major (72 chunks of (tap kk, 32c))
// ---------------------------------------------------------------------------
__global__ void k0_wth(const float* __restrict__ dw)
{
    const int og = blockIdx.x / 72, ch = blockIdx.x % 72;
    const int kk = ch >> 3, c0 = (ch & 7) * 32;
    for (int t = threadIdx.x; t < 1024; t += 256) {
        int j = t & 7, lane = (t >> 3) & 31, m = (t >> 8) & 1, s = t >> 9;
        int r = lane >> 2, q = lane & 3;
        int o = og * 32 + m * 16 + r + ((j >> 1) & 1) * 8;
        int kl = s * 16 + (j >> 2) * 8 + q * 2 + (j & 1);
        int c = c0 + kl;
        g_wth[(size_t)blockIdx.x * 1024 + t] =
            __float2half_rn(dw[(size_t)o * 2304 + c * 9 + kk]);
    }
}

// ---------------------------------------------------------------------------
// Kernel 0b: conv1 weights -> fp16 fragment-major (16 chunks of 32c)
// ---------------------------------------------------------------------------
__global__ void k0_w1h(const float* __restrict__ w1)
{
    const int og = blockIdx.x >> 4, ch = blockIdx.x & 15;
    for (int t = threadIdx.x; t < 1024; t += 256) {
        int j = t & 7, lane = (t >> 3) & 31, m = (t >> 8) & 1, s = t >> 9;
        int r = lane >> 2, q = lane & 3;
        int o = og * 32 + m * 16 + r + ((j >> 1) & 1) * 8;
        int c = ch * 32 + s * 16 + (j >> 2) * 8 + q * 2 + (j & 1);
        g_w1th[(size_t)blockIdx.x * 1024 + t] = __float2half_rn(w1[(size_t)o * 512 + c]);
    }
}

// ---------------------------------------------------------------------------
// Kernel 0c: offset-conv weights (18 pad 32) -> fp16 fragment-major
// ---------------------------------------------------------------------------
__global__ void k0_w2h(const float* __restrict__ ow)
{
    const int ch = blockIdx.x;
    const int kk = ch >> 3, c0 = (ch & 7) * 32;
    for (int t = threadIdx.x; t < 1024; t += 256) {
        int j = t & 7, lane = (t >> 3) & 31, m = (t >> 8) & 1, s = t >> 9;
        int r = lane >> 2, q = lane & 3;
        int o = m * 16 + r + ((j >> 1) & 1) * 8;
        int kl = s * 16 + (j >> 2) * 8 + q * 2 + (j & 1);
        int c = c0 + kl;
        float v = (o < 18) ? ow[(size_t)o * 2304 + c * 9 + kk] : 0.f;
        g_w2th[(size_t)ch * 1024 + t] = __float2half_rn(v);
    }
}

// ---------------------------------------------------------------------------
// Kernel 1: conv1 via mma.sync fp16 + BN1 + upsample + attention fuse.
// 512 threads, tile 256 m x 64 px, grid (49, 8). K=512 in 16 chunks of 32.
// A: fp16 cp.async ring. B: fp32 x cp.async ring, packed to half2 at use.
// ---------------------------------------------------------------------------
#define X_PITCH 72
// byte offsets in dynamic smem
#define K1_OFS_W   0                 // 3 x 8192 halves = 49152 B
#define K1_OFS_X   49152             // 3 x 2304 floats = 27648 B
#define K1_OFS_AW  76800             // 1024 floats = 4096 B
#define K1_OFS_RED 80896             // 1024 floats = 4096 B
#define K1_OFS_ZS  84992             // 128 floats  = 512 B
#define K1_OFS_SI  85504             // 64 ints     = 256 B
#define K1_BYTES   85760
#define T_PITCH 260

__global__ __launch_bounds__(512, 1)
void k1_mma(const float* __restrict__ x, const float* __restrict__ y,
            const float* __restrict__ g1, const float* __restrict__ b1,
            const float* __restrict__ mu1, const float* __restrict__ v1,
            const float* __restrict__ attw, const float* __restrict__ attb,
            float* __restrict__ xf_nchw)
{
    extern __shared__ char smc[];
    __half* wbuf = (__half*)(smc + K1_OFS_W);
    float*  xbuf = (float*)(smc + K1_OFS_X);
    float*  aw   = (float*)(smc + K1_OFS_AW);
    float*  red  = (float*)(smc + K1_OFS_RED);
    float*  zs   = (float*)(smc + K1_OFS_ZS);
    int*    si   = (int*)(smc + K1_OFS_SI);
    const uint32_t sB = smem_u32(smc);

    const int n   = blockIdx.y;
    const int p0  = blockIdx.x * 64;
    const int tid = threadIdx.x;
    const int wid = tid >> 5;
    const int lane = tid & 31;

    for (int i = tid; i < 1024; i += 512) aw[i] = attw[i];
    if (tid < 64) {
        int pg = p0 + tid;
        int hh = pg / 56, ww = pg % 56;
        si[tid] = (hh >> 1) * 28 + (ww >> 1);
    }

    const float* xb = x + (size_t)n * CIN * P_;
    const int xc  = tid >> 4, xseg = tid & 15;

    auto wi = [&](int slot, int ch) {
#pragma unroll
        for (int gl = 0; gl < 2; gl++) {
            int f = (gl * 512 + tid) * 8;        // half index 0..8184
            int og = f >> 10, inner = f & 1023;
            cp_async16(sB + (uint32_t)(K1_OFS_W + (slot * 8192 + f) * 2),
                       g_w1th + ((size_t)og * 16 + ch) * 1024 + inner);
        }
    };
    auto xi = [&](int slot, int ch) {
        cp_async16(sB + (uint32_t)(K1_OFS_X + (slot * 2304 + xc * X_PITCH + xseg * 4) * 4),
                   xb + (size_t)(ch * 32 + xc) * P_ + p0 + xseg * 4);
    };

    float acc[2][4][4];
#pragma unroll
    for (int m = 0; m < 2; m++)
#pragma unroll
        for (int t = 0; t < 4; t++)
#pragma unroll
            for (int c = 0; c < 4; c++) acc[m][t][c] = 0.f;

    wi(0, 0); xi(0, 0); CP_COMMIT();
    wi(1, 1); xi(1, 1); CP_COMMIT();
    CP_WAIT1();
    __syncthreads();

    const int g    = wid >> 1;
    const int px0  = (wid & 1) * 32;
    const int qrow = lane >> 2;
    const int qcol = lane & 3;

    for (int ch = 0; ch < 16; ch++) {
        int slot = ch % 3;
        bool more2 = (ch + 2 < 16);
        if (more2) { wi((ch + 2) % 3, ch + 2); xi((ch + 2) % 3, ch + 2); CP_COMMIT(); }
        const __half* Ab = wbuf + slot * 8192 + g * 1024;
        const float* Xc = xbuf + slot * 2304;
#pragma unroll
        for (int s = 0; s < 2; s++) {
            uint4 av0 = *(const uint4*)(Ab + s * 512 + lane * 8);
            uint4 av1 = *(const uint4*)(Ab + s * 512 + 256 + lane * 8);
            uint32_t bb[4][2];
            const float* xr = Xc + (s * 16 + qcol * 2) * X_PITCH + px0 + qrow;
#pragma unroll
            for (int t = 0; t < 4; t++) {
                float f0 = xr[t * 8];
                float f1 = xr[X_PITCH + t * 8];
                float f8 = xr[8 * X_PITCH + t * 8];
                float f9 = xr[9 * X_PITCH + t * 8];
                bb[t][0] = pack_h2(f0, f1);
                bb[t][1] = pack_h2(f8, f9);
            }
#pragma unroll
            for (int t = 0; t < 4; t++) {
                mma_fp16(acc[0][t], (const uint32_t*)&av0, bb[t]);
                mma_fp16(acc[1][t], (const uint32_t*)&av1, bb[t]);
            }
        }
        if (more2) { CP_WAIT1(); }
        else if (ch + 1 < 16) { CP_WAIT0(); }
        __syncthreads();
    }

    // ---- epilogue: BN1 + attention + sigmoid + xf ----
    const float* yb = y + (size_t)n * MID * PY_;
    float t0p[8], t1p[8];
#pragma unroll
    for (int pj = 0; pj < 8; pj++) { t0p[pj] = 0.f; t1p[pj] = 0.f; }

#pragma unroll
    for (int m = 0; m < 2; m++) {
#pragma unroll
        for (int rh = 0; rh < 2; rh++) {
            int o = g * 32 + m * 16 + rh * 8 + qrow;
            float sc = g1[o] * rsqrtf(v1[o] + EPSF);
            float bi = b1[o] - mu1[o] * sc;
            float axm0 = aw[o], ayu0 = aw[256 + o];
            float axm1 = aw[512 + o], ayu1 = aw[768 + o];
#pragma unroll
            for (int t = 0; t < 4; t++) {
#pragma unroll
                for (int j = 0; j < 2; j++) {
                    int pj = t * 2 + j;
                    int p = px0 + t * 8 + qcol * 2 + j;
                    float xv = fmaf(acc[m][t][rh * 2 + j], sc, bi);
                    acc[m][t][rh * 2 + j] = xv;
                    float yv = yb[(size_t)o * PY_ + si[p]];
                    t0p[pj] = fmaf(axm0, xv, fmaf(ayu0, yv, t0p[pj]));
                    t1p[pj] = fmaf(axm1, xv, fmaf(ayu1, yv, t1p[pj]));
                }
            }
        }
    }
#pragma unroll
    for (int pj = 0; pj < 8; pj++) {
#pragma unroll
        for (int off = 4; off < 32; off <<= 1) {
            t0p[pj] += __shfl_xor_sync(0xffffffffu, t0p[pj], off);
            t1p[pj] += __shfl_xor_sync(0xffffffffu, t1p[pj], off);
        }
    }
    if (qrow == 0) {
#pragma unroll
        for (int t = 0; t < 4; t++)
#pragma unroll
            for (int j = 0; j < 2; j++) {
                int p = px0 + t * 8 + qcol * 2 + j;
                red[g * 64 + p]       = t0p[t * 2 + j];
                red[512 + g * 64 + p] = t1p[t * 2 + j];
            }
    }
    __syncthreads();
    if (tid < 128) {
        int which = tid & 1, p = tid >> 1;
        float s = 0.f;
#pragma unroll
        for (int gg = 0; gg < 8; gg++) s += red[which * 512 + gg * 64 + p];
        zs[which * 64 + p] = 1.f / (1.f + expf(-(s + attb[which])));
    }
    __syncthreads();

    float* trans = (float*)smc;   // overlay W+X rings: 64*260*4 = 66560 B < 76800
#pragma unroll
    for (int m = 0; m < 2; m++) {
#pragma unroll
        for (int rh = 0; rh < 2; rh++) {
            int o = g * 32 + m * 16 + rh * 8 + qrow;
#pragma unroll
            for (int t = 0; t < 4; t++) {
#pragma unroll
                for (int j = 0; j < 2; j++) {
                    int p = px0 + t * 8 + qcol * 2 + j;
                    float yv = yb[(size_t)o * PY_ + si[p]];
                    float xfv = acc[m][t][rh * 2 + j] * zs[p] + yv * zs[64 + p];
                    trans[p * T_PITCH + o] = xfv;
                }
            }
        }
    }
    __syncthreads();

    {
        int p = tid >> 3, c0 = (tid & 7) * 32;
        float* dst = g_nhwc + ((size_t)n * P_ + p0 + p) * 256 + c0;
        const float* src = trans + p * T_PITCH + c0;
#pragma unroll
        for (int u = 0; u < 8; u++)
            *(float4*)(dst + u * 4) = *(const float4*)(src + u * 4);
    }
    {
        int o = tid >> 1, half = tid & 1;
        float* dst = xf_nchw + ((size_t)(n * 256 + o)) * P_ + p0 + half * 32;
#pragma unroll
        for (int u = 0; u < 8; u++) {
            float4 v;
            v.x = trans[(half * 32 + u * 4 + 0) * T_PITCH + o];
            v.y = trans[(half * 32 + u * 4 + 1) * T_PITCH + o];
            v.z = trans[(half * 32 + u * 4 + 2) * T_PITCH + o];
            v.w = trans[(half * 32 + u * 4 + 3) * T_PITCH + o];
            *(float4*)(dst + u * 4) = v;
        }
    }
}

// ---------------------------------------------------------------------------
// Kernel 2: offset conv3x3 via mma.sync fp16. 2 rows/block, 512 thr, grid (28,8).
// (unchanged R10)
// ---------------------------------------------------------------------------
__global__ __launch_bounds__(512)
void k2_mma()
{
    __shared__ __half sa[3 * 1024];
    __shared__ __half sb[2 * 5120];
    const uint32_t sAu = smem_u32(sa);

    const int h2 = blockIdx.x, n = blockIdx.y;
    const int tid = threadIdx.x, wid = tid >> 5, lane = tid & 31;
    const int qrow = lane >> 2, qcol = lane & 3;

    const float* nh = g_nhwc + (size_t)n * P_ * 256;
    const int fp = tid >> 2;
    const int cg = (tid & 3) * 8;
    const int rowl = fp >> 6, colf = fp & 63;
    const int base_sp = (cg >> 4) * 16 + ((cg >> 3) & 1) * 2;

    float acc[2][4];
#pragma unroll
    for (int m = 0; m < 2; m++)
#pragma unroll
        for (int c = 0; c < 4; c++) acc[m][c] = 0.f;

    float st0[8], st1[8];

    auto a_issue = [&](int slot, int ch) {
        if (tid < 128)
            cp_async16(sAu + (uint32_t)(slot * 1024 + tid * 8) * 2,
                       g_w2th + (size_t)ch * 1024 + tid * 8);
        CP_COMMIT();
    };
    auto b_issue = [&](float* st, int ch) {
        int kk = ch >> 3, c0 = (ch & 7) * 32;
        int dy = kk / 3 - 1, dx = kk % 3 - 1;
        int rr = h2 * 2 + rowl + dy, xx = colf + dx;
        bool valid = (rr >= 0) && (rr < 56) && (xx >= 0) && (xx < 56) && (colf < 56);
        if (valid) {
            const float* src = nh + ((size_t)(rr * 56 + xx)) * 256 + c0 + cg;
            *(float4*)(st)     = *(const float4*)(src);
            *(float4*)(st + 4) = *(const float4*)(src + 4);
        } else {
#pragma unroll
            for (int i = 0; i < 8; i++) st[i] = 0.f;
        }
    };
    auto b_combine = [&](const float* st, int ch) {
        __half* dst = sb + (ch & 1) * 5120 + fp * 40;
#pragma unroll
        for (int i = 0; i < 4; i++) {
            __half2 hv = __floats2half2_rn(st[2 * i], st[2 * i + 1]);
            *(__half2*)(dst + base_sp + i * 4) = hv;
        }
    };
    auto do_mma = [&](int ch) {
        const __half* Ab = sa + (ch % 3) * 1024;
        const __half* Sb2 = sb + (ch & 1) * 5120;
#pragma unroll
        for (int s = 0; s < 2; s++) {
            uint4 av0 = *(const uint4*)(Ab + s * 512 + lane * 8);
            uint4 av1 = *(const uint4*)(Ab + s * 512 + 256 + lane * 8);
            uint2 bv = *(const uint2*)(Sb2 + (wid * 8 + qrow) * 40 + s * 16 + qcol * 4);
            mma_fp16(acc[0], (const uint32_t*)&av0, (const uint32_t*)&bv);
            mma_fp16(acc[1], (const uint32_t*)&av1, (const uint32_t*)&bv);
        }
    };

    a_issue(0, 0);
    a_issue(1, 1);
    b_issue(st0, 0);
    b_issue(st1, 1);
    b_combine(st0, 0);
    CP_WAIT1();
    __syncthreads();

    auto iter = [&](int ch, float* stCur, float* stOther) {
        bool more2 = (ch + 2 < 72);
        if (more2) {
            a_issue((ch + 2) % 3, ch + 2);
            b_issue(stCur, ch + 2);
        }
        if (ch + 1 < 72) b_combine(stOther, ch + 1);
        do_mma(ch);
        if (more2) { CP_WAIT1(); }
        else if (ch + 1 < 72) { CP_WAIT0(); }
        __syncthreads();
    };
    for (int c2 = 0; c2 < 72; c2 += 2) {
        iter(c2,     st0, st1);
        iter(c2 + 1, st1, st0);
    }

#pragma unroll
    for (int m = 0; m < 2; m++) {
#pragma unroll
        for (int rh = 0; rh < 2; rh++) {
            int o = m * 16 + rh * 8 + qrow;
            int px = wid * 8 + qcol * 2;
            int rr = h2 * 2 + (px >> 6), col = px & 63;
            if (o < 18 && col < 56) {
                float* ob = g_off + ((size_t)(n * 18 + o)) * P_ + rr * 56 + col;
                ob[0] = acc[m][rh * 2 + 0];
                ob[1] = acc[m][rh * 2 + 1];
            }
        }
    }
}

// ---------------------------------------------------------------------------
// Kernel 3: deformable conv via mma.sync fp16, deep pipeline. (unchanged R10)
// ---------------------------------------------------------------------------
#define K3_WCH 8192
#define K3_SCH 2560
#define K3_OFS_W   0
#define K3_OFS_S   49152
#define K3_OFS_MW  59392
#define K3_OFS_MO  68608
#define K3_BYTES   77824

__global__ __launch_bounds__(512, 1)
void k3_mma(const float* __restrict__ g2, const float* __restrict__ b2,
            const float* __restrict__ mu2, const float* __restrict__ v2,
            float* __restrict__ out)
{
    extern __shared__ char smc[];
    __half* wbuf = (__half*)(smc + K3_OFS_W);
    __half* sbuf = (__half*)(smc + K3_OFS_S);
    float4* mw4  = (float4*)(smc + K3_OFS_MW);
    int4*   mo4  = (int4*)(smc + K3_OFS_MO);
    const uint32_t sW = smem_u32(smc);

    const int n   = blockIdx.y;
    const int p0  = blockIdx.x * 64;
    const int tid = threadIdx.x;
    const int wid = tid >> 5;
    const int lane = tid & 31;

    for (int e = tid; e < 576; e += 512) {
        int p = e / 9, k = e - p * 9;
        int pg = p0 + p;
        int ph = pg / 56, pw = pg % 56;
        float dy = g_off[((size_t)(n * 18 + 2 * k)) * P_ + pg];
        float dx = g_off[((size_t)(n * 18 + 2 * k + 1)) * P_ + pg];
        float sy = (float)(ph - 1 + k / 3) + dy;
        float sx = (float)(pw - 1 + k % 3) + dx;
        float y0f = floorf(sy), x0f = floorf(sx);
        float wy1 = sy - y0f, wx1 = sx - x0f;
        int iy0 = (int)y0f, ix0 = (int)x0f;
        bool vy0 = (iy0 >= 0) && (iy0 <= 55);
        bool vy1 = (iy0 + 1 >= 0) && (iy0 + 1 <= 55);
        bool vx0 = (ix0 >= 0) && (ix0 <= 55);
        bool vx1 = (ix0 + 1 >= 0) && (ix0 + 1 <= 55);
        int y0c = min(max(iy0, 0), 55),     y1c = min(max(iy0 + 1, 0), 55);
        int x0c = min(max(ix0, 0), 55),     x1c = min(max(ix0 + 1, 0), 55);
        float4 w;
        w.x = (vy0 && vx0) ? (1.f - wy1) * (1.f - wx1) : 0.f;
        w.y = (vy0 && vx1) ? (1.f - wy1) * wx1 : 0.f;
        w.z = (vy1 && vx0) ? wy1 * (1.f - wx1) : 0.f;
        w.w = (vy1 && vx1) ? wy1 * wx1 : 0.f;
        int4 oo;
        oo.x = (y0c * 56 + x0c) * 256;
        oo.y = (y0c * 56 + x1c) * 256;
        oo.z = (y1c * 56 + x0c) * 256;
        oo.w = (y1c * 56 + x1c) * 256;
        mw4[e] = w;
        mo4[e] = oo;
    }
    __syncthreads();

    const float* nh = g_nhwc + (size_t)n * P_ * 256;
    const int g    = wid >> 1;
    const int px0  = (wid & 1) * 32;
    const int qrow = lane >> 2;
    const int qcol = lane & 3;
    const int sp = ((lane >> 1) & 3) * 4 + ((lane >> 3) & 1) * 2 + (lane & 1)
                 + (lane >> 4) * 16;

    float acc[2][4][4];
#pragma unroll
    for (int m = 0; m < 2; m++)
#pragma unroll
        for (int t = 0; t < 4; t++)
#pragma unroll
            for (int c = 0; c < 4; c++) acc[m][t][c] = 0.f;

    float st0[16], st1[16];

    auto weights_issue = [&](int slot, int ch) {
#pragma unroll
        for (int gl = 0; gl < 2; gl++) {
            int f = (gl * 512 + tid) * 8;
            int og = f >> 10, inner = f & 1023;
            cp_async16(sW + (uint32_t)(K3_OFS_W + (slot * K3_WCH + f) * 2),
                       g_wth + ((size_t)og * 72 + ch) * 1024 + inner);
        }
        CP_COMMIT();
    };
    auto gather_issue = [&](float* st, int ch) {
        const int kk = ch >> 3;
        const int ci = ((ch & 7) * 32) + lane;
#pragma unroll
        for (int i = 0; i < 4; i++) {
            int p = wid * 4 + i;
            int4 oo = mo4[p * 9 + kk];
            st[i*4+0] = nh[oo.x + ci];
            st[i*4+1] = nh[oo.y + ci];
            st[i*4+2] = nh[oo.z + ci];
            st[i*4+3] = nh[oo.w + ci];
        }
    };
    auto combine = [&](const float* st, int ch) {
        const int kk = ch >> 3;
        __half* dst = sbuf + (ch & 1) * K3_SCH;
#pragma unroll
        for (int i = 0; i < 4; i++) {
            int p = wid * 4 + i;
            float4 w = mw4[p * 9 + kk];
            float v = w.x * st[i*4+0] + w.y * st[i*4+1]
                    + w.z * st[i*4+2] + w.w * st[i*4+3];
            dst[p * 40 + sp] = __float2half_rn(v);
        }
    };
    auto do_mma = [&](int ch) {
        const __half* Ab = wbuf + (ch % 3) * K3_WCH + g * 1024;
        const __half* Sb = sbuf + (ch & 1) * K3_SCH;
#pragma unroll
        for (int s = 0; s < 2; s++) {
            uint4 av0 = *(const uint4*)(Ab + s * 512 + lane * 8);
            uint4 av1 = *(const uint4*)(Ab + s * 512 + 256 + lane * 8);
            uint2 bv[4];
            const __half* sr = Sb + (px0 + qrow) * 40 + s * 16 + qcol * 4;
#pragma unroll
            for (int t = 0; t < 4; t++)
                bv[t] = *(const uint2*)(sr + t * 8 * 40);
#pragma unroll
            for (int t = 0; t < 4; t++) {
                mma_fp16(acc[0][t], (const uint32_t*)&av0, (const uint32_t*)&bv[t]);
                mma_fp16(acc[1][t], (const uint32_t*)&av1, (const uint32_t*)&bv[t]);
            }
        }
    };

    weights_issue(0, 0);
    weights_issue(1, 1);
    gather_issue(st0, 0);
    gather_issue(st1, 1);
    combine(st0, 0);
    CP_WAIT1();
    __syncthreads();

    auto iter = [&](int ch, float* stCur, float* stOther) {
        bool more2 = (ch + 2 < 72);
        if (more2) {
            weights_issue((ch + 2) % 3, ch + 2);
            gather_issue(stCur, ch + 2);
        }
        if (ch + 1 < 72) combine(stOther, ch + 1);
        do_mma(ch);
        if (more2) { CP_WAIT1(); }
        else if (ch + 1 < 72) { CP_WAIT0(); }
        __syncthreads();
    };
    for (int c2 = 0; c2 < 72; c2 += 2) {
        iter(c2,     st0, st1);
        iter(c2 + 1, st1, st0);
    }

#pragma unroll
    for (int m = 0; m < 2; m++) {
#pragma unroll
        for (int rh = 0; rh < 2; rh++) {
            int o = g * 32 + m * 16 + rh * 8 + qrow;
            float sc = g2[o] * rsqrtf(v2[o] + EPSF);
            float bi = b2[o] - mu2[o] * sc;
            float* ob = out + ((size_t)(n * 256 + o)) * P_ + p0 + px0;
#pragma unroll
            for (int t = 0; t < 4; t++) {
                float2 v;
                v.x = fmaf(acc[m][t][rh * 2 + 0], sc, bi);
                v.y = fmaf(acc[m][t][rh * 2 + 1], sc, bi);
                *(float2*)(ob + t * 8 + 2 * qcol) = v;
            }
        }
    }
}

// ---------------------------------------------------------------------------
extern "C" void kernel_launch(void* const* d_in, const int* in_sizes, int n_in,
                              void* d_out, int out_size)
{
    const float* x       = (const float*)d_in[0];
    const float* y       = (const float*)d_in[1];
    const float* conv1_w = (const float*)d_in[2];
    const float* bn1_g   = (const float*)d_in[3];
    const float* bn1_b   = (const float*)d_in[4];
    const float* bn1_m   = (const float*)d_in[5];
    const float* bn1_v   = (const float*)d_in[6];
    const float* att_w   = (const float*)d_in[7];
    const float* att_b   = (const float*)d_in[8];
    const float* off_w   = (const float*)d_in[9];
    const float* dcn_w   = (const float*)d_in[10];
    const float* bn2_g   = (const float*)d_in[11];
    const float* bn2_b   = (const float*)d_in[12];
    const float* bn2_m   = (const float*)d_in[13];
    const float* bn2_v   = (const float*)d_in[14];

    float* out = (float*)d_out;
    const size_t one = (size_t)N_ * OUTC * P_;  // 6,422,528

    float* xf_nchw;
    if ((size_t)out_size >= 2 * one) {
        xf_nchw = out + one;  // tuple (out, xf) flattened
    } else {
        void* p = nullptr;
        cudaGetSymbolAddress(&p, g_xf_scratch);
        xf_nchw = (float*)p;
    }

    cudaFuncSetAttribute(k1_mma, cudaFuncAttributeMaxDynamicSharedMemorySize, 96 * 1024);
    cudaFuncSetAttribute(k3_mma, cudaFuncAttributeMaxDynamicSharedMemorySize, 80 * 1024);

    k0_wth<<<576, 256>>>(dcn_w);
    k0_w1h<<<128, 256>>>(conv1_w);
    k0_w2h<<<72, 256>>>(off_w);

    k1_mma<<<dim3(49, 8), 512, K1_BYTES>>>(x, y, bn1_g, bn1_b, bn1_m, bn1_v,
                                           att_w, att_b, xf_nchw);

    k2_mma<<<dim3(28, 8), 512>>>();

    k3_mma<<<dim3(49, 8), 512, K3_BYTES>>>(bn2_g, bn2_b, bn2_m, bn2_v, out);
}

// round 17
// speedup vs baseline: 2.4964x; 1.0311x over previous
#include <cuda_runtime.h>
#include <cuda_fp16.h>
#include <math.h>
#include <stdint.h>

#define N_   8
#define CIN  512
#define MID  256
#define OUTC 256
#define H_   56
#define W_   56
#define P_   3136
#define PY_  784
#define EPSF 1e-5f

// Scratch (static device globals; no allocation allowed)
__device__ float  g_nhwc[(size_t)N_ * P_ * MID];       // xf in NHWC for gather
__device__ float  g_off[(size_t)N_ * 18 * P_];         // offsets
__device__ float  g_xf_scratch[(size_t)N_ * MID * P_]; // xf NCHW fallback
__device__ __half g_wth[(size_t)OUTC * 2304];          // dcn weights fp16 fragment-major
__device__ __half g_w1th[(size_t)MID * CIN];           // conv1 weights fp16 fragment-major
__device__ __half g_w2th[(size_t)72 * 1024];           // offset-conv weights fp16 (M pad 32)

// ---------------------------------------------------------------------------
// helpers (family-safe PTX only: sm_80+ instructions)
// ---------------------------------------------------------------------------
__device__ __forceinline__ void mma_fp16(float* d, const uint32_t* a, const uint32_t* b) {
    asm volatile(
        "mma.sync.aligned.m16n8k16.row.col.f32.f16.f16.f32 "
        "{%0,%1,%2,%3}, {%4,%5,%6,%7}, {%8,%9}, {%0,%1,%2,%3};"
        : "+f"(d[0]), "+f"(d[1]), "+f"(d[2]), "+f"(d[3])
        : "r"(a[0]), "r"(a[1]), "r"(a[2]), "r"(a[3]), "r"(b[0]), "r"(b[1]));
}
__device__ __forceinline__ uint32_t pack_h2(float lo, float hi) {
    uint32_t r;
    asm("cvt.rn.f16x2.f32 %0, %1, %2;" : "=r"(r) : "f"(hi), "f"(lo));
    return r;
}
__device__ __forceinline__ uint32_t smem_u32(const void* p) {
    uint32_t a;
    asm("{ .reg .u64 t; cvta.to.shared.u64 t, %1; cvt.u32.u64 %0, t; }" : "=r"(a) : "l"(p));
    return a;
}
__device__ __forceinline__ void cp_async16(uint32_t dst, const void* src) {
    asm volatile("cp.async.cg.shared.global [%0], [%1], 16;" :: "r"(dst), "l"(src));
}
#define CP_COMMIT() asm volatile("cp.async.commit_group;" ::: "memory")
#define CP_WAIT0()  asm volatile("cp.async.wait_group 0;" ::: "memory")
#define CP_WAIT1()  asm volatile("cp.async.wait_group 1;" ::: "memory")

// ---------------------------------------------------------------------------
// Kernel 0: all weight rearrangements fused in one launch.
// blocks 0..575: dcn; 576..703: conv1; 704..775: offset conv.
// ---------------------------------------------------------------------------
__global__ void k0_all(const float* __restrict__ dw, const float* __restrict__ w1,
                       const float* __restrict__ ow)
{
    int b = blockIdx.x;
    if (b < 576) {
        const int og = b / 72, ch = b % 72;
        const int kk = ch >> 3, c0 = (ch & 7) * 32;
        for (int t = threadIdx.x; t < 1024; t += 256) {
            int j = t & 7, lane = (t >> 3) & 31, m = (t >> 8) & 1, s = t >> 9;
            int r = lane >> 2, q = lane & 3;
            int o = og * 32 + m * 16 + r + ((j >> 1) & 1) * 8;
            int c = c0 + s * 16 + (j >> 2) * 8 + q * 2 + (j & 1);
            g_wth[(size_t)b * 1024 + t] = __float2half_rn(dw[(size_t)o * 2304 + c * 9 + kk]);
        }
    } else if (b < 704) {
        int bb = b - 576;
        const int og = bb >> 4, ch = bb & 15;
        for (int t = threadIdx.x; t < 1024; t += 256) {
            int j = t & 7, lane = (t >> 3) & 31, m = (t >> 8) & 1, s = t >> 9;
            int r = lane >> 2, q = lane & 3;
            int o = og * 32 + m * 16 + r + ((j >> 1) & 1) * 8;
            int c = ch * 32 + s * 16 + (j >> 2) * 8 + q * 2 + (j & 1);
            g_w1th[(size_t)bb * 1024 + t] = __float2half_rn(w1[(size_t)o * 512 + c]);
        }
    } else {
        int ch = b - 704;
        const int kk = ch >> 3, c0 = (ch & 7) * 32;
        for (int t = threadIdx.x; t < 1024; t += 256) {
            int j = t & 7, lane = (t >> 3) & 31, m = (t >> 8) & 1, s = t >> 9;
            int r = lane >> 2, q = lane & 3;
            int o = m * 16 + r + ((j >> 1) & 1) * 8;
            int c = c0 + s * 16 + (j >> 2) * 8 + q * 2 + (j & 1);
            float v = (o < 18) ? ow[(size_t)o * 2304 + c * 9 + kk] : 0.f;
            g_w2th[(size_t)ch * 1024 + t] = __float2half_rn(v);
        }
    }
}

// ---------------------------------------------------------------------------
// Kernel 1: conv1 via mma.sync fp16 + BN1 + upsample + attention fuse.
// B path: fp32 x ring -> per-chunk fp16 k-paired combine buffer (shared by all
// warps) -> LDS.64 fragments.
// RACE FIX vs R13: combine(ch+1) reads OTHER threads' cp.async data, so it
// must run AFTER (wait_group + __syncthreads), with a second barrier before
// the next mma consumes hbuf.
// ---------------------------------------------------------------------------
#define X_PITCH 72
// byte offsets in dynamic smem
#define K1_OFS_W   0                 // 3 x 8192 halves = 49152 B
#define K1_OFS_X   49152             // 3 x 2304 floats = 27648 B
#define K1_OFS_H   76800             // 2 x 2560 halves = 10240 B
#define K1_OFS_AW  87040             // 1024 floats = 4096 B
#define K1_OFS_RED 91136             // 1024 floats = 4096 B
#define K1_OFS_ZS  95232             // 128 floats  = 512 B
#define K1_OFS_SI  95744             // 64 ints     = 256 B
#define K1_BYTES   96000
#define T_PITCH 260

__global__ __launch_bounds__(512, 1)
void k1_mma(const float* __restrict__ x, const float* __restrict__ y,
            const float* __restrict__ g1, const float* __restrict__ b1,
            const float* __restrict__ mu1, const float* __restrict__ v1,
            const float* __restrict__ attw, const float* __restrict__ attb,
            float* __restrict__ xf_nchw)
{
    extern __shared__ char smc[];
    __half* wbuf = (__half*)(smc + K1_OFS_W);
    float*  xbuf = (float*)(smc + K1_OFS_X);
    __half* hbuf = (__half*)(smc + K1_OFS_H);
    float*  aw   = (float*)(smc + K1_OFS_AW);
    float*  red  = (float*)(smc + K1_OFS_RED);
    float*  zs   = (float*)(smc + K1_OFS_ZS);
    int*    si   = (int*)(smc + K1_OFS_SI);
    const uint32_t sB = smem_u32(smc);

    const int n   = blockIdx.y;
    const int p0  = blockIdx.x * 64;
    const int tid = threadIdx.x;
    const int wid = tid >> 5;
    const int lane = tid & 31;

    for (int i = tid; i < 1024; i += 512) aw[i] = attw[i];
    if (tid < 64) {
        int pg = p0 + tid;
        int hh = pg / 56, ww = pg % 56;
        si[tid] = (hh >> 1) * 28 + (ww >> 1);
    }

    const float* xb = x + (size_t)n * CIN * P_;
    const int xc  = tid >> 4, xseg = tid & 15;

    auto wi = [&](int slot, int ch) {
#pragma unroll
        for (int gl = 0; gl < 2; gl++) {
            int f = (gl * 512 + tid) * 8;        // half index 0..8184
            int og = f >> 10, inner = f & 1023;
            cp_async16(sB + (uint32_t)(K1_OFS_W + (slot * 8192 + f) * 2),
                       g_w1th + ((size_t)og * 16 + ch) * 1024 + inner);
        }
    };
    auto xi = [&](int slot, int ch) {
        cp_async16(sB + (uint32_t)(K1_OFS_X + (slot * 2304 + xc * X_PITCH + xseg * 4) * 4),
                   xb + (size_t)(ch * 32 + xc) * P_ + p0 + xseg * 4);
    };
    // combine: fp32 [c][p] (pitch 72) -> fp16 k-paired [p][40]
    const int cpp = tid >> 3;        // pixel 0..63
    const int ckp = tid & 7;         // k-pair base (handles ckp and ckp+8)
    auto combine = [&](int ch) {
        const float* src = xbuf + (ch % 3) * 2304;
        __half* dst = hbuf + (ch & 1) * 2560 + cpp * 40;
#pragma unroll
        for (int u = 0; u < 2; u++) {
            int kp = ckp + u * 8;            // pair index 0..15
            int k0 = kp * 2;
            float f0 = src[k0 * X_PITCH + cpp];
            float f1 = src[(k0 + 1) * X_PITCH + cpp];
            int sp = ((k0 >> 1) & 3) * 4 + ((k0 >> 3) & 1) * 2 + (k0 >> 4) * 16;
            *(uint32_t*)(dst + sp) = pack_h2(f0, f1);
        }
    };

    float acc[2][4][4];
#pragma unroll
    for (int m = 0; m < 2; m++)
#pragma unroll
        for (int t = 0; t < 4; t++)
#pragma unroll
            for (int c = 0; c < 4; c++) acc[m][t][c] = 0.f;

    wi(0, 0); xi(0, 0); CP_COMMIT();
    wi(1, 1); xi(1, 1); CP_COMMIT();
    CP_WAIT1();              // group 0 complete (this thread)
    __syncthreads();         // group 0 visible to all threads
    combine(0);
    __syncthreads();

    const int g    = wid >> 1;
    const int px0  = (wid & 1) * 32;
    const int qrow = lane >> 2;
    const int qcol = lane & 3;

    for (int ch = 0; ch < 16; ch++) {
        bool more2 = (ch + 2 < 16);
        if (more2) { wi((ch + 2) % 3, ch + 2); xi((ch + 2) % 3, ch + 2); CP_COMMIT(); }
        // MMA on chunk ch from hbuf[ch&1] + wbuf slot ch%3
        {
            const __half* Ab = wbuf + (ch % 3) * 8192 + g * 1024;
            const __half* Sb = hbuf + (ch & 1) * 2560;
#pragma unroll
            for (int s = 0; s < 2; s++) {
                uint4 av0 = *(const uint4*)(Ab + s * 512 + lane * 8);
                uint4 av1 = *(const uint4*)(Ab + s * 512 + 256 + lane * 8);
                uint2 bv[4];
                const __half* sr = Sb + (px0 + qrow) * 40 + s * 16 + qcol * 4;
#pragma unroll
                for (int t = 0; t < 4; t++)
                    bv[t] = *(const uint2*)(sr + t * 8 * 40);
#pragma unroll
                for (int t = 0; t < 4; t++) {
                    mma_fp16(acc[0][t], (const uint32_t*)&av0, (const uint32_t*)&bv[t]);
                    mma_fp16(acc[1][t], (const uint32_t*)&av1, (const uint32_t*)&bv[t]);
                }
            }
        }
        if (more2) { CP_WAIT1(); }
        else if (ch + 1 < 16) { CP_WAIT0(); }
        __syncthreads();     // make chunk ch+1 x data (other threads' copies) visible
        if (ch + 1 < 16) {
            combine(ch + 1);
            __syncthreads(); // hbuf[(ch+1)&1] ready before next mma
        }
    }

    // ---- epilogue: BN1 + attention + sigmoid + xf ----
    const float* yb = y + (size_t)n * MID * PY_;
    float t0p[8], t1p[8];
#pragma unroll
    for (int pj = 0; pj < 8; pj++) { t0p[pj] = 0.f; t1p[pj] = 0.f; }

#pragma unroll
    for (int m = 0; m < 2; m++) {
#pragma unroll
        for (int rh = 0; rh < 2; rh++) {
            int o = g * 32 + m * 16 + rh * 8 + qrow;
            float sc = g1[o] * rsqrtf(v1[o] + EPSF);
            float bi = b1[o] - mu1[o] * sc;
            float axm0 = aw[o], ayu0 = aw[256 + o];
            float axm1 = aw[512 + o], ayu1 = aw[768 + o];
#pragma unroll
            for (int t = 0; t < 4; t++) {
#pragma unroll
                for (int j = 0; j < 2; j++) {
                    int pj = t * 2 + j;
                    int p = px0 + t * 8 + qcol * 2 + j;
                    float xv = fmaf(acc[m][t][rh * 2 + j], sc, bi);
                    acc[m][t][rh * 2 + j] = xv;
                    float yv = yb[(size_t)o * PY_ + si[p]];
                    t0p[pj] = fmaf(axm0, xv, fmaf(ayu0, yv, t0p[pj]));
                    t1p[pj] = fmaf(axm1, xv, fmaf(ayu1, yv, t1p[pj]));
                }
            }
        }
    }
#pragma unroll
    for (int pj = 0; pj < 8; pj++) {
#pragma unroll
        for (int off = 4; off < 32; off <<= 1) {
            t0p[pj] += __shfl_xor_sync(0xffffffffu, t0p[pj], off);
            t1p[pj] += __shfl_xor_sync(0xffffffffu, t1p[pj], off);
        }
    }
    if (qrow == 0) {
#pragma unroll
        for (int t = 0; t < 4; t++)
#pragma unroll
            for (int j = 0; j < 2; j++) {
                int p = px0 + t * 8 + qcol * 2 + j;
                red[g * 64 + p]       = t0p[t * 2 + j];
                red[512 + g * 64 + p] = t1p[t * 2 + j];
            }
    }
    __syncthreads();
    if (tid < 128) {
        int which = tid & 1, p = tid >> 1;
        float s = 0.f;
#pragma unroll
        for (int gg = 0; gg < 8; gg++) s += red[which * 512 + gg * 64 + p];
        zs[which * 64 + p] = 1.f / (1.f + expf(-(s + attb[which])));
    }
    __syncthreads();

    float* trans = (float*)smc;   // overlay W+X rings: 64*260*4 = 66560 B
#pragma unroll
    for (int m = 0; m < 2; m++) {
#pragma unroll
        for (int rh = 0; rh < 2; rh++) {
            int o = g * 32 + m * 16 + rh * 8 + qrow;
#pragma unroll
            for (int t = 0; t < 4; t++) {
#pragma unroll
                for (int j = 0; j < 2; j++) {
                    int p = px0 + t * 8 + qcol * 2 + j;
                    float yv = yb[(size_t)o * PY_ + si[p]];
                    float xfv = acc[m][t][rh * 2 + j] * zs[p] + yv * zs[64 + p];
                    trans[p * T_PITCH + o] = xfv;
                }
            }
        }
    }
    __syncthreads();

    {
        int p = tid >> 3, c0 = (tid & 7) * 32;
        float* dst = g_nhwc + ((size_t)n * P_ + p0 + p) * 256 + c0;
        const float* src = trans + p * T_PITCH + c0;
#pragma unroll
        for (int u = 0; u < 8; u++)
            *(float4*)(dst + u * 4) = *(const float4*)(src + u * 4);
    }
    {
        int o = tid >> 1, half = tid & 1;
        float* dst = xf_nchw + ((size_t)(n * 256 + o)) * P_ + p0 + half * 32;
#pragma unroll
        for (int u = 0; u < 8; u++) {
            float4 v;
            v.x = trans[(half * 32 + u * 4 + 0) * T_PITCH + o];
            v.y = trans[(half * 32 + u * 4 + 1) * T_PITCH + o];
            v.z = trans[(half * 32 + u * 4 + 2) * T_PITCH + o];
            v.w = trans[(half * 32 + u * 4 + 3) * T_PITCH + o];
            *(float4*)(dst + u * 4) = v;
        }
    }
}

// ---------------------------------------------------------------------------
// Kernel 2: offset conv3x3 via mma.sync fp16. 2 rows/block, 512 thr, grid (28,8).
// (unchanged R10 — no cross-thread async reads, race-free)
// ---------------------------------------------------------------------------
__global__ __launch_bounds__(512)
void k2_mma()
{
    __shared__ __half sa[3 * 1024];
    __shared__ __half sb[2 * 5120];
    const uint32_t sAu = smem_u32(sa);

    const int h2 = blockIdx.x, n = blockIdx.y;
    const int tid = threadIdx.x, wid = tid >> 5, lane = tid & 31;
    const int qrow = lane >> 2, qcol = lane & 3;

    const float* nh = g_nhwc + (size_t)n * P_ * 256;
    const int fp = tid >> 2;
    const int cg = (tid & 3) * 8;
    const int rowl = fp >> 6, colf = fp & 63;
    const int base_sp = (cg >> 4) * 16 + ((cg >> 3) & 1) * 2;

    float acc[2][4];
#pragma unroll
    for (int m = 0; m < 2; m++)
#pragma unroll
        for (int c = 0; c < 4; c++) acc[m][c] = 0.f;

    float st0[8], st1[8];

    auto a_issue = [&](int slot, int ch) {
        if (tid < 128)
            cp_async16(sAu + (uint32_t)(slot * 1024 + tid * 8) * 2,
                       g_w2th + (size_t)ch * 1024 + tid * 8);
        CP_COMMIT();
    };
    auto b_issue = [&](float* st, int ch) {
        int kk = ch >> 3, c0 = (ch & 7) * 32;
        int dy = kk / 3 - 1, dx = kk % 3 - 1;
        int rr = h2 * 2 + rowl + dy, xx = colf + dx;
        bool valid = (rr >= 0) && (rr < 56) && (xx >= 0) && (xx < 56) && (colf < 56);
        if (valid) {
            const float* src = nh + ((size_t)(rr * 56 + xx)) * 256 + c0 + cg;
            *(float4*)(st)     = *(const float4*)(src);
            *(float4*)(st + 4) = *(const float4*)(src + 4);
        } else {
#pragma unroll
            for (int i = 0; i < 8; i++) st[i] = 0.f;
        }
    };
    auto b_combine = [&](const float* st, int ch) {
        __half* dst = sb + (ch & 1) * 5120 + fp * 40;
#pragma unroll
        for (int i = 0; i < 4; i++) {
            __half2 hv = __floats2half2_rn(st[2 * i], st[2 * i + 1]);
            *(__half2*)(dst + base_sp + i * 4) = hv;
        }
    };
    auto do_mma = [&](int ch) {
        const __half* Ab = sa + (ch % 3) * 1024;
        const __half* Sb2 = sb + (ch & 1) * 5120;
#pragma unroll
        for (int s = 0; s < 2; s++) {
            uint4 av0 = *(const uint4*)(Ab + s * 512 + lane * 8);
            uint4 av1 = *(const uint4*)(Ab + s * 512 + 256 + lane * 8);
            uint2 bv = *(const uint2*)(Sb2 + (wid * 8 + qrow) * 40 + s * 16 + qcol * 4);
            mma_fp16(acc[0], (const uint32_t*)&av0, (const uint32_t*)&bv);
            mma_fp16(acc[1], (const uint32_t*)&av1, (const uint32_t*)&bv);
        }
    };

    a_issue(0, 0);
    a_issue(1, 1);
    b_issue(st0, 0);
    b_issue(st1, 1);
    b_combine(st0, 0);
    CP_WAIT1();
    __syncthreads();

    auto iter = [&](int ch, float* stCur, float* stOther) {
        bool more2 = (ch + 2 < 72);
        if (more2) {
            a_issue((ch + 2) % 3, ch + 2);
            b_issue(stCur, ch + 2);
        }
        if (ch + 1 < 72) b_combine(stOther, ch + 1);
        do_mma(ch);
        if (more2) { CP_WAIT1(); }
        else if (ch + 1 < 72) { CP_WAIT0(); }
        __syncthreads();
    };
    for (int c2 = 0; c2 < 72; c2 += 2) {
        iter(c2,     st0, st1);
        iter(c2 + 1, st1, st0);
    }

#pragma unroll
    for (int m = 0; m < 2; m++) {
#pragma unroll
        for (int rh = 0; rh < 2; rh++) {
            int o = m * 16 + rh * 8 + qrow;
            int px = wid * 8 + qcol * 2;
            int rr = h2 * 2 + (px >> 6), col = px & 63;
            if (o < 18 && col < 56) {
                float* ob = g_off + ((size_t)(n * 18 + o)) * P_ + rr * 56 + col;
                ob[0] = acc[m][rh * 2 + 0];
                ob[1] = acc[m][rh * 2 + 1];
            }
        }
    }
}

// ---------------------------------------------------------------------------
// Kernel 3: deformable conv via mma.sync fp16, deep pipeline. (unchanged R10)
// ---------------------------------------------------------------------------
#define K3_WCH 8192
#define K3_SCH 2560
#define K3_OFS_W   0
#define K3_OFS_S   49152
#define K3_OFS_MW  59392
#define K3_OFS_MO  68608
#define K3_BYTES   77824

__global__ __launch_bounds__(512, 1)
void k3_mma(const float* __restrict__ g2, const float* __restrict__ b2,
            const float* __restrict__ mu2, const float* __restrict__ v2,
            float* __restrict__ out)
{
    extern __shared__ char smc[];
    __half* wbuf = (__half*)(smc + K3_OFS_W);
    __half* sbuf = (__half*)(smc + K3_OFS_S);
    float4* mw4  = (float4*)(smc + K3_OFS_MW);
    int4*   mo4  = (int4*)(smc + K3_OFS_MO);
    const uint32_t sW = smem_u32(smc);

    const int n   = blockIdx.y;
    const int p0  = blockIdx.x * 64;
    const int tid = threadIdx.x;
    const int wid = tid >> 5;
    const int lane = tid & 31;

    for (int e = tid; e < 576; e += 512) {
        int p = e / 9, k = e - p * 9;
        int pg = p0 + p;
        int ph = pg / 56, pw = pg % 56;
        float dy = g_off[((size_t)(n * 18 + 2 * k)) * P_ + pg];
        float dx = g_off[((size_t)(n * 18 + 2 * k + 1)) * P_ + pg];
        float sy = (float)(ph - 1 + k / 3) + dy;
        float sx = (float)(pw - 1 + k % 3) + dx;
        float y0f = floorf(sy), x0f = floorf(sx);
        float wy1 = sy - y0f, wx1 = sx - x0f;
        int iy0 = (int)y0f, ix0 = (int)x0f;
        bool vy0 = (iy0 >= 0) && (iy0 <= 55);
        bool vy1 = (iy0 + 1 >= 0) && (iy0 + 1 <= 55);
        bool vx0 = (ix0 >= 0) && (ix0 <= 55);
        bool vx1 = (ix0 + 1 >= 0) && (ix0 + 1 <= 55);
        int y0c = min(max(iy0, 0), 55),     y1c = min(max(iy0 + 1, 0), 55);
        int x0c = min(max(ix0, 0), 55),     x1c = min(max(ix0 + 1, 0), 55);
        float4 w;
        w.x = (vy0 && vx0) ? (1.f - wy1) * (1.f - wx1) : 0.f;
        w.y = (vy0 && vx1) ? (1.f - wy1) * wx1 : 0.f;
        w.z = (vy1 && vx0) ? wy1 * (1.f - wx1) : 0.f;
        w.w = (vy1 && vx1) ? wy1 * wx1 : 0.f;
        int4 oo;
        oo.x = (y0c * 56 + x0c) * 256;
        oo.y = (y0c * 56 + x1c) * 256;
        oo.z = (y1c * 56 + x0c) * 256;
        oo.w = (y1c * 56 + x1c) * 256;
        mw4[e] = w;
        mo4[e] = oo;
    }
    __syncthreads();

    const float* nh = g_nhwc + (size_t)n * P_ * 256;
    const int g    = wid >> 1;
    const int px0  = (wid & 1) * 32;
    const int qrow = lane >> 2;
    const int qcol = lane & 3;
    const int sp = ((lane >> 1) & 3) * 4 + ((lane >> 3) & 1) * 2 + (lane & 1)
                 + (lane >> 4) * 16;

    float acc[2][4][4];
#pragma unroll
    for (int m = 0; m < 2; m++)
#pragma unroll
        for (int t = 0; t < 4; t++)
#pragma unroll
            for (int c = 0; c < 4; c++) acc[m][t][c] = 0.f;

    float st0[16], st1[16];

    auto weights_issue = [&](int slot, int ch) {
#pragma unroll
        for (int gl = 0; gl < 2; gl++) {
            int f = (gl * 512 + tid) * 8;
            int og = f >> 10, inner = f & 1023;
            cp_async16(sW + (uint32_t)(K3_OFS_W + (slot * K3_WCH + f) * 2),
                       g_wth + ((size_t)og * 72 + ch) * 1024 + inner);
        }
        CP_COMMIT();
    };
    auto gather_issue = [&](float* st, int ch) {
        const int kk = ch >> 3;
        const int ci = ((ch & 7) * 32) + lane;
#pragma unroll
        for (int i = 0; i < 4; i++) {
            int p = wid * 4 + i;
            int4 oo = mo4[p * 9 + kk];
            st[i*4+0] = nh[oo.x + ci];
            st[i*4+1] = nh[oo.y + ci];
            st[i*4+2] = nh[oo.z + ci];
            st[i*4+3] = nh[oo.w + ci];
        }
    };
    auto combine = [&](const float* st, int ch) {
        const int kk = ch >> 3;
        __half* dst = sbuf + (ch & 1) * K3_SCH;
#pragma unroll
        for (int i = 0; i < 4; i++) {
            int p = wid * 4 + i;
            float4 w = mw4[p * 9 + kk];
            float v = w.x * st[i*4+0] + w.y * st[i*4+1]
                    + w.z * st[i*4+2] + w.w * st[i*4+3];
            dst[p * 40 + sp] = __float2half_rn(v);
        }
    };
    auto do_mma = [&](int ch) {
        const __half* Ab = wbuf + (ch % 3) * K3_WCH + g * 1024;
        const __half* Sb = sbuf + (ch & 1) * K3_SCH;
#pragma unroll
        for (int s = 0; s < 2; s++) {
            uint4 av0 = *(const uint4*)(Ab + s * 512 + lane * 8);
            uint4 av1 = *(const uint4*)(Ab + s * 512 + 256 + lane * 8);
            uint2 bv[4];
            const __half* sr = Sb + (px0 + qrow) * 40 + s * 16 + qcol * 4;
#pragma unroll
            for (int t = 0; t < 4; t++)
                bv[t] = *(const uint2*)(sr + t * 8 * 40);
#pragma unroll
            for (int t = 0; t < 4; t++) {
                mma_fp16(acc[0][t], (const uint32_t*)&av0, (const uint32_t*)&bv[t]);
                mma_fp16(acc[1][t], (const uint32_t*)&av1, (const uint32_t*)&bv[t]);
            }
        }
    };

    weights_issue(0, 0);
    weights_issue(1, 1);
    gather_issue(st0, 0);
    gather_issue(st1, 1);
    combine(st0, 0);
    CP_WAIT1();
    __syncthreads();

    auto iter = [&](int ch, float* stCur, float* stOther) {
        bool more2 = (ch + 2 < 72);
        if (more2) {
            weights_issue((ch + 2) % 3, ch + 2);
            gather_issue(stCur, ch + 2);
        }
        if (ch + 1 < 72) combine(stOther, ch + 1);
        do_mma(ch);
        if (more2) { CP_WAIT1(); }
        else if (ch + 1 < 72) { CP_WAIT0(); }
        __syncthreads();
    };
    for (int c2 = 0; c2 < 72; c2 += 2) {
        iter(c2,     st0, st1);
        iter(c2 + 1, st1, st0);
    }

#pragma unroll
    for (int m = 0; m < 2; m++) {
#pragma unroll
        for (int rh = 0; rh < 2; rh++) {
            int o = g * 32 + m * 16 + rh * 8 + qrow;
            float sc = g2[o] * rsqrtf(v2[o] + EPSF);
            float bi = b2[o] - mu2[o] * sc;
            float* ob = out + ((size_t)(n * 256 + o)) * P_ + p0 + px0;
#pragma unroll
            for (int t = 0; t < 4; t++) {
                float2 v;
                v.x = fmaf(acc[m][t][rh * 2 + 0], sc, bi);
                v.y = fmaf(acc[m][t][rh * 2 + 1], sc, bi);
                *(float2*)(ob + t * 8 + 2 * qcol) = v;
            }
        }
    }
}

// ---------------------------------------------------------------------------
extern "C" void kernel_launch(void* const* d_in, const int* in_sizes, int n_in,
                              void* d_out, int out_size)
{
    const float* x       = (const float*)d_in[0];
    const float* y       = (const float*)d_in[1];
    const float* conv1_w = (const float*)d_in[2];
    const float* bn1_g   = (const float*)d_in[3];
    const float* bn1_b   = (const float*)d_in[4];
    const float* bn1_m   = (const float*)d_in[5];
    const float* bn1_v   = (const float*)d_in[6];
    const float* att_w   = (const float*)d_in[7];
    const float* att_b   = (const float*)d_in[8];
    const float* off_w   = (const float*)d_in[9];
    const float* dcn_w   = (const float*)d_in[10];
    const float* bn2_g   = (const float*)d_in[11];
    const float* bn2_b   = (const float*)d_in[12];
    const float* bn2_m   = (const float*)d_in[13];
    const float* bn2_v   = (const float*)d_in[14];

    float* out = (float*)d_out;
    const size_t one = (size_t)N_ * OUTC * P_;  // 6,422,528

    float* xf_nchw;
    if ((size_t)out_size >= 2 * one) {
        xf_nchw = out + one;  // tuple (out, xf) flattened
    } else {
        void* p = nullptr;
        cudaGetSymbolAddress(&p, g_xf_scratch);
        xf_nchw = (float*)p;
    }

    cudaFuncSetAttribute(k1_mma, cudaFuncAttributeMaxDynamicSharedMemorySize, 100 * 1024);
    cudaFuncSetAttribute(k3_mma, cudaFuncAttributeMaxDynamicSharedMemorySize, 80 * 1024);

    k0_all<<<776, 256>>>(dcn_w, conv1_w, off_w);

    k1_mma<<<dim3(49, 8), 512, K1_BYTES>>>(x, y, bn1_g, bn1_b, bn1_m, bn1_v,
                                           att_w, att_b, xf_nchw);

    k2_mma<<<dim3(28, 8), 512>>>();

    k3_mma<<<dim3(49, 8), 512, K3_BYTES>>>(bn2_g, bn2_b, bn2_m, bn2_v, out);
}